// round 15
// baseline (speedup 1.0000x reference)
#include <cuda_runtime.h>
#include <cuda_bf16.h>
#include <cstdint>

// ---------------------------------------------------------------------------
// FAVOR+ (Performer) attention. Shapes: B=2, T=4096, d=1024, h=16, m=256, dk=64.
// All GEMM-shaped stages on mma.sync bf16 split-x3 (compute_103-safe).
// tc_gemm: 64x128 CTA tile, 96KB smem -> 2 CTAs/SM; pass-major MMA ordering
// (hh/hl/lh separated) so accumulator RAW chains have distance 8, not 1.
// ---------------------------------------------------------------------------

#define Bc   2
#define Hc   16
#define Tc   4096
#define DKc  64
#define Mc   256
#define Dc   1024
#define BHc  (Bc*Hc)     // 32
#define BTc  (Bc*Tc)     // 8192
#define NCHUNK 32
#define NAUG 72          // KV cols (64) + Ksum col + pad to mult of 8

#define EPSc        1e-6f
#define INV_SQRT_M  0.0625f
#define INV_SQRT_DK 0.125f

// ------------------------- device scratch ----------------------------------
__device__ float g_V   [BHc*Tc*DKc];
__device__ float g_phiK[BHc*Tc*Mc];
__device__ float g_KVp [NCHUNK*BHc*Mc*DKc];
__device__ float g_Ksp [NCHUNK*BHc*Mc];

__device__ __align__(16) __nv_bfloat16 g_Qh[BHc*Tc*DKc], g_Ql[BHc*Tc*DKc];
__device__ __align__(16) __nv_bfloat16 g_Kh[BHc*Tc*DKc], g_Kl[BHc*Tc*DKc];
__device__ __align__(16) __nv_bfloat16 g_pQh[BHc*Tc*Mc], g_pQl[BHc*Tc*Mc];
__device__ __align__(16) __nv_bfloat16 g_kvh[BHc*NAUG*Mc], g_kvl[BHc*NAUG*Mc];
__device__ __align__(16) __nv_bfloat16 g_ph[Hc*Mc*DKc],  g_pl[Hc*Mc*DKc];

__device__ __align__(16) __nv_bfloat16 g_xhi[BTc*Dc],  g_xlo[BTc*Dc];
__device__ __align__(16) __nv_bfloat16 g_mhi[BTc*Dc],  g_mlo[BTc*Dc];
__device__ __align__(16) __nv_bfloat16 g_wqh[Dc*Dc], g_wql[Dc*Dc];
__device__ __align__(16) __nv_bfloat16 g_wkh[Dc*Dc], g_wkl[Dc*Dc];
__device__ __align__(16) __nv_bfloat16 g_wvh[Dc*Dc], g_wvl[Dc*Dc];
__device__ __align__(16) __nv_bfloat16 g_woh[Dc*Dc], g_wol[Dc*Dc];

// ------------------------- helpers -----------------------------------------
__device__ __forceinline__ uint32_t smem_u32(const void* p) {
    uint32_t a;
    asm("{ .reg .u64 t; cvta.to.shared.u64 t, %1; cvt.u32.u64 %0, t; }"
        : "=r"(a) : "l"(p));
    return a;
}

__device__ __forceinline__ uint32_t swz_b(uint32_t off) {
    return off ^ ((off >> 3) & 0x70);
}

__device__ __forceinline__ void ldsm_x4(uint32_t* r, uint32_t addr) {
    asm volatile("ldmatrix.sync.aligned.m8n8.x4.shared.b16 {%0,%1,%2,%3}, [%4];"
                 : "=r"(r[0]), "=r"(r[1]), "=r"(r[2]), "=r"(r[3]) : "r"(addr));
}

__device__ __forceinline__ void mma_bf16(float* d, const uint32_t* a, const uint32_t* b) {
    asm volatile(
        "mma.sync.aligned.m16n8k16.row.col.f32.bf16.bf16.f32 "
        "{%0,%1,%2,%3}, {%4,%5,%6,%7}, {%8,%9}, {%0,%1,%2,%3};"
        : "+f"(d[0]), "+f"(d[1]), "+f"(d[2]), "+f"(d[3])
        : "r"(a[0]), "r"(a[1]), "r"(a[2]), "r"(a[3]), "r"(b[0]), "r"(b[1]));
}

__device__ __forceinline__ void split_store(__nv_bfloat16* hp, __nv_bfloat16* lp,
                                            size_t idx, float a, float b) {
    __nv_bfloat16 ha = __float2bfloat16(a), hb = __float2bfloat16(b);
    __nv_bfloat16 la = __float2bfloat16(a - __bfloat162float(ha));
    __nv_bfloat16 lb = __float2bfloat16(b - __bfloat162float(hb));
    *(__nv_bfloat162*)(hp + idx) = __nv_bfloat162{ha, hb};
    *(__nv_bfloat162*)(lp + idx) = __nv_bfloat162{la, lb};
}

// cp.async rows of 64 bf16 (128B) into swizzled smem tile. src pre-offset.
template <int NT>
__device__ __forceinline__ void cpa_g(const __nv_bfloat16* __restrict__ src, int ldk,
                                      uint32_t dst, int tid, int nchunks) {
    for (int g = tid; g < nchunks; g += NT) {
        int row = g >> 3, cg = g & 7;
        const void* gp = src + (size_t)row * ldk + cg * 8;
        uint32_t d = dst + swz_b((uint32_t)(row * 128 + cg * 16));
        asm volatile("cp.async.cg.shared.global [%0], [%1], 16;"
                     :: "r"(d), "l"(gp) : "memory");
    }
}

#define CPA_COMMIT() asm volatile("cp.async.commit_group;" ::: "memory")
#define CPA_WAIT(n)  asm volatile("cp.async.wait_group %0;" :: "n"(n) : "memory")

// ------------------------- split fp32 -> bf16 hi/lo ------------------------
__device__ __forceinline__ void split_body(const float* __restrict__ src,
                                           __nv_bfloat16* __restrict__ hi,
                                           __nv_bfloat16* __restrict__ lo, int i)
{
    float4 v = ((const float4*)src)[i];
    __nv_bfloat16 h0 = __float2bfloat16(v.x);
    __nv_bfloat16 h1 = __float2bfloat16(v.y);
    __nv_bfloat16 h2 = __float2bfloat16(v.z);
    __nv_bfloat16 h3 = __float2bfloat16(v.w);
    __nv_bfloat16 l0 = __float2bfloat16(v.x - __bfloat162float(h0));
    __nv_bfloat16 l1 = __float2bfloat16(v.y - __bfloat162float(h1));
    __nv_bfloat16 l2 = __float2bfloat16(v.z - __bfloat162float(h2));
    __nv_bfloat16 l3 = __float2bfloat16(v.w - __bfloat162float(h3));
    __nv_bfloat162* hp = (__nv_bfloat162*)hi;
    __nv_bfloat162* lp = (__nv_bfloat162*)lo;
    hp[2*i]   = __nv_bfloat162{h0, h1};
    hp[2*i+1] = __nv_bfloat162{h2, h3};
    lp[2*i]   = __nv_bfloat162{l0, l1};
    lp[2*i+1] = __nv_bfloat162{l2, l3};
}

__global__ __launch_bounds__(256) void split_kernel(const float* __restrict__ src,
                                                    __nv_bfloat16* __restrict__ hi,
                                                    __nv_bfloat16* __restrict__ lo,
                                                    int n4)
{
    int i = blockIdx.x * 256 + threadIdx.x;
    if (i < n4) split_body(src, hi, lo, i);
}

// fused split of the four d x d weight matrices (z selects)
__global__ __launch_bounds__(256) void wsplit_kernel(
    const float* __restrict__ s0, const float* __restrict__ s1,
    const float* __restrict__ s2, const float* __restrict__ s3,
    __nv_bfloat16* h0, __nv_bfloat16* l0, __nv_bfloat16* h1, __nv_bfloat16* l1,
    __nv_bfloat16* h2, __nv_bfloat16* l2, __nv_bfloat16* h3, __nv_bfloat16* l3)
{
    int i = blockIdx.x * 256 + threadIdx.x;
    if (i >= Dc * Dc / 4) return;
    int z = blockIdx.y;
    const float* s = (z == 0) ? s0 : (z == 1) ? s1 : (z == 2) ? s2 : s3;
    __nv_bfloat16* h = (z == 0) ? h0 : (z == 1) ? h1 : (z == 2) ? h2 : h3;
    __nv_bfloat16* l = (z == 0) ? l0 : (z == 1) ? l1 : (z == 2) ? l2 : l3;
    split_body(s, h, l, i);
}

// ---------------------------------------------------------------------------
// Big GEMM: C[M,N] = A[M,K] @ W[N,K]^T, K = 1024, bf16 split-x3.
// CTA tile 64(M) x 128(N), BK=64, 2-stage: 48KB/stage = 96KB -> 2 CTAs/SM.
// 256 threads, warp grid 2M x 4N, warp tile 32x32. Pass-major MMA order.
// MODE 0: z picks Wq/Wk/Wv; z<2 writes bf16 hi/lo head-transposed scaled;
//         z=2 writes V fp32 head-transposed.
// MODE 1: Wo + bias -> plain [BT,D] fp32 to d_out.
// ---------------------------------------------------------------------------
#define GSTAGE 49152
template <int MODE>
__global__ __launch_bounds__(256, 2) void tc_gemm(
    const __nv_bfloat16* __restrict__ Ahi, const __nv_bfloat16* __restrict__ Alo,
    const __nv_bfloat16* __restrict__ W0h, const __nv_bfloat16* __restrict__ W0l,
    const __nv_bfloat16* __restrict__ W1h, const __nv_bfloat16* __restrict__ W1l,
    const __nv_bfloat16* __restrict__ W2h, const __nv_bfloat16* __restrict__ W2l,
    const float* __restrict__ bias, float* __restrict__ Oplain)
{
    extern __shared__ char smem[];
    const uint32_t sbase = smem_u32(smem);
    const int tid = threadIdx.x, wid = tid >> 5, lane = tid & 31;
    const int bn = blockIdx.x * 128, bm = blockIdx.y * 64;
    const int z = (MODE == 0) ? blockIdx.z : 0;

    const __nv_bfloat16 *Bh, *Bl;
    float scale = 1.0f;
    if (MODE == 0) {
        Bh = (z == 0) ? W0h : ((z == 1) ? W1h : W2h);
        Bl = (z == 0) ? W0l : ((z == 1) ? W1l : W2l);
        scale = (z < 2) ? INV_SQRT_DK : 1.0f;
    } else {
        Bh = W0h; Bl = W0l;
    }

    auto load_stage = [&](int c, int stg) {
        uint32_t st = sbase + (uint32_t)stg * (uint32_t)GSTAGE;
        int k0 = c * 64;
        cpa_g<256>(Ahi + (size_t)bm * Dc + k0, Dc, st,          tid, 512);
        cpa_g<256>(Alo + (size_t)bm * Dc + k0, Dc, st + 8192,   tid, 512);
        cpa_g<256>(Bh  + (size_t)bn * Dc + k0, Dc, st + 16384,  tid, 1024);
        cpa_g<256>(Bl  + (size_t)bn * Dc + k0, Dc, st + 32768,  tid, 1024);
        CPA_COMMIT();
    };

    float acc[2][4][4];
#pragma unroll
    for (int a = 0; a < 2; a++)
#pragma unroll
        for (int b = 0; b < 4; b++)
#pragma unroll
            for (int c = 0; c < 4; c++) acc[a][b][c] = 0.0f;

    const int wm = wid & 1, wn = wid >> 1;
    const uint32_t arow = (uint32_t)(wm * 32 + (lane & 15));
    const uint32_t akh  = (uint32_t)((lane >> 4) << 3);
    const uint32_t brow = (uint32_t)(wn * 32 + ((lane >> 4) << 3) + (lane & 7));
    const uint32_t bkh  = (uint32_t)(lane & 8);

    load_stage(0, 0);

    for (int c = 0; c < 16; c++) {
        if (c + 1 < 16) { load_stage(c + 1, (c + 1) & 1); CPA_WAIT(1); }
        else            { CPA_WAIT(0); }
        __syncthreads();

        const uint32_t st = sbase + (uint32_t)(c & 1) * (uint32_t)GSTAGE;
#pragma unroll
        for (int ks = 0; ks < 4; ks++) {
            uint32_t ah[2][4], al[2][4], bhf[2][4], blf[2][4];
#pragma unroll
            for (int mb = 0; mb < 2; mb++) {
                uint32_t off = swz_b((arow + mb * 16) * 128 + (ks * 16 + akh) * 2);
                ldsm_x4(ah[mb], st + off);
                ldsm_x4(al[mb], st + 8192 + off);
            }
#pragma unroll
            for (int nb2 = 0; nb2 < 2; nb2++) {
                uint32_t off = swz_b((brow + nb2 * 16) * 128 + (ks * 16 + bkh) * 2);
                ldsm_x4(bhf[nb2], st + 16384 + off);
                ldsm_x4(blf[nb2], st + 32768 + off);
            }
            // pass-major: hh over all 8 accs, then hl, then lh (RAW distance 8)
#pragma unroll
            for (int mb = 0; mb < 2; mb++)
#pragma unroll
                for (int nb = 0; nb < 4; nb++)
                    mma_bf16(acc[mb][nb], ah[mb], &bhf[nb >> 1][(nb & 1) * 2]);
#pragma unroll
            for (int mb = 0; mb < 2; mb++)
#pragma unroll
                for (int nb = 0; nb < 4; nb++)
                    mma_bf16(acc[mb][nb], ah[mb], &blf[nb >> 1][(nb & 1) * 2]);
#pragma unroll
            for (int mb = 0; mb < 2; mb++)
#pragma unroll
                for (int nb = 0; nb < 4; nb++)
                    mma_bf16(acc[mb][nb], al[mb], &bhf[nb >> 1][(nb & 1) * 2]);
        }
        __syncthreads();
    }

    // ---- epilogue ----
    const int group = lane >> 2, tig = lane & 3;
#pragma unroll
    for (int mb = 0; mb < 2; mb++) {
        int m0 = bm + wm * 32 + mb * 16 + group;
#pragma unroll
        for (int nb = 0; nb < 4; nb++) {
            int n0 = bn + wn * 32 + nb * 8 + tig * 2;
            float* d = acc[mb][nb];
            if (MODE == 0) {
                int head = n0 >> 6, dd = n0 & 63;
                int bb = m0 >> 12, t = m0 & (Tc - 1);
                size_t base = ((((size_t)bb * Hc + head) * Tc) + t) * DKc + dd;
                if (z == 2) {
                    *(float2*)(g_V + base)            = make_float2(d[0], d[1]);
                    *(float2*)(g_V + base + 8 * DKc)  = make_float2(d[2], d[3]);
                } else {
                    __nv_bfloat16* qh = z ? g_Kh : g_Qh;
                    __nv_bfloat16* ql = z ? g_Kl : g_Ql;
                    split_store(qh, ql, base,           d[0] * scale, d[1] * scale);
                    split_store(qh, ql, base + 8 * DKc, d[2] * scale, d[3] * scale);
                }
            } else {
                float2 bv = *(const float2*)(bias + n0);
                float* o = Oplain + (size_t)m0 * Dc + n0;
                *(float2*)o           = make_float2(d[0] + bv.x, d[1] + bv.y);
                *(float2*)(o + 8*Dc)  = make_float2(d[2] + bv.x, d[3] + bv.y);
            }
        }
    }
}

// ---------------------------------------------------------------------------
// phi via mma: xw[128t x 256m] = X[128 x 64] @ proj[256 x 64]^T (split-x3),
// then rowmax/exp epilogue. z=0: X=Q -> phiQ bf16 hi/lo; z=1: X=K -> phiK f32.
// Pass-interleaved (distance 4) within each nb2 pair.
// ---------------------------------------------------------------------------
__global__ __launch_bounds__(256, 1) void phi_mma()
{
    extern __shared__ char smem[];
    const uint32_t sbase = smem_u32(smem);
    const int tid = threadIdx.x, wid = tid >> 5, lane = tid & 31;
    const int bh = blockIdx.x, tile = blockIdx.y, z = blockIdx.z;
    const int h = bh & (Hc - 1);

    const __nv_bfloat16* Ah = z ? g_Kh : g_Qh;
    const __nv_bfloat16* Al = z ? g_Kl : g_Ql;

    const size_t abase = ((size_t)bh * Tc + tile * 128) * DKc;
    cpa_g<256>(Ah + abase, DKc, sbase,         tid, 1024);
    cpa_g<256>(Al + abase, DKc, sbase + 16384, tid, 1024);
    const size_t pbase = (size_t)h * Mc * DKc;
    cpa_g<256>(g_ph + pbase, DKc, sbase + 32768, tid, 2048);
    cpa_g<256>(g_pl + pbase, DKc, sbase + 65536, tid, 2048);
    CPA_COMMIT();
    CPA_WAIT(0);
    __syncthreads();

    float acc[32][4];
#pragma unroll
    for (int nb = 0; nb < 32; nb++)
#pragma unroll
        for (int j = 0; j < 4; j++) acc[nb][j] = 0.0f;

    const int m0 = wid * 16;
    const uint32_t arow = (uint32_t)(m0 + (lane & 15));
    const uint32_t akh  = (uint32_t)((lane >> 4) << 3);
    const uint32_t brw  = (uint32_t)(((lane >> 4) << 3) + (lane & 7));
    const uint32_t bkh  = (uint32_t)(lane & 8);

#pragma unroll
    for (int ks = 0; ks < 4; ks++) {
        uint32_t ah[4], al[4];
        uint32_t aoff = swz_b(arow * 128 + (ks * 16 + akh) * 2);
        ldsm_x4(ah, sbase + aoff);
        ldsm_x4(al, sbase + 16384 + aoff);
#pragma unroll
        for (int nb4 = 0; nb4 < 8; nb4++) {   // two nb2 iterations fused -> 4 accs
            uint32_t b4h[2][4], b4l[2][4];
#pragma unroll
            for (int q = 0; q < 2; q++) {
                uint32_t boff = swz_b(((nb4 * 2 + q) * 16 + brw) * 128 + (ks * 16 + bkh) * 2);
                ldsm_x4(b4h[q], sbase + 32768 + boff);
                ldsm_x4(b4l[q], sbase + 65536 + boff);
            }
            // pass-major over 4 accumulators (distance 4)
#pragma unroll
            for (int q = 0; q < 2; q++)
#pragma unroll
                for (int w = 0; w < 2; w++)
                    mma_bf16(acc[(nb4 * 2 + q) * 2 + w], ah, &b4h[q][w * 2]);
#pragma unroll
            for (int q = 0; q < 2; q++)
#pragma unroll
                for (int w = 0; w < 2; w++)
                    mma_bf16(acc[(nb4 * 2 + q) * 2 + w], ah, &b4l[q][w * 2]);
#pragma unroll
            for (int q = 0; q < 2; q++)
#pragma unroll
                for (int w = 0; w < 2; w++)
                    mma_bf16(acc[(nb4 * 2 + q) * 2 + w], al, &b4h[q][w * 2]);
        }
    }

    // ---- epilogue: rowmax, xnorm, exp, store ----
    const int group = lane >> 2, tig = lane & 3;
    float mx0 = -1e30f, mx1 = -1e30f;
#pragma unroll
    for (int nb = 0; nb < 32; nb++) {
        mx0 = fmaxf(mx0, fmaxf(acc[nb][0], acc[nb][1]));
        mx1 = fmaxf(mx1, fmaxf(acc[nb][2], acc[nb][3]));
    }
#pragma unroll
    for (int o = 1; o < 4; o <<= 1) {
        mx0 = fmaxf(mx0, __shfl_xor_sync(0xffffffffu, mx0, o));
        mx1 = fmaxf(mx1, __shfl_xor_sync(0xffffffffu, mx1, o));
    }

    auto rowsq = [&](int r) -> float {
        float s = 0.0f;
#pragma unroll
        for (int cg = 0; cg < 8; cg++) {
            uint32_t off = swz_b((uint32_t)(r * 128 + cg * 16));
            uint4 hv = *(const uint4*)(smem + off);
            uint4 lv = *(const uint4*)(smem + 16384 + off);
            const __nv_bfloat162* hp = (const __nv_bfloat162*)&hv;
            const __nv_bfloat162* lp = (const __nv_bfloat162*)&lv;
#pragma unroll
            for (int j = 0; j < 4; j++) {
                float2 hf = __bfloat1622float2(hp[j]);
                float2 lf = __bfloat1622float2(lp[j]);
                float a = hf.x + lf.x, b = hf.y + lf.y;
                s += a * a + b * b;
            }
        }
        return s;
    };
    const int r0l = m0 + group, r1l = r0l + 8;
    float e0 = expf(-0.5f * rowsq(r0l));
    float e1 = expf(-0.5f * rowsq(r1l));

    const size_t idx0 = ((size_t)bh * Tc + tile * 128 + r0l) * Mc;
    const size_t idx1 = ((size_t)bh * Tc + tile * 128 + r1l) * Mc;
#pragma unroll
    for (int nb = 0; nb < 32; nb++) {
        int col = nb * 8 + tig * 2;
        float v00 = (expf(acc[nb][0] - mx0) * e0 + EPSc) * INV_SQRT_M;
        float v01 = (expf(acc[nb][1] - mx0) * e0 + EPSc) * INV_SQRT_M;
        float v10 = (expf(acc[nb][2] - mx1) * e1 + EPSc) * INV_SQRT_M;
        float v11 = (expf(acc[nb][3] - mx1) * e1 + EPSc) * INV_SQRT_M;
        if (z == 0) {
            split_store(g_pQh, g_pQl, idx0 + col, v00, v01);
            split_store(g_pQh, g_pQl, idx1 + col, v10, v11);
        } else {
            *(float2*)(g_phiK + idx0 + col) = make_float2(v00, v01);
            *(float2*)(g_phiK + idx1 + col) = make_float2(v10, v11);
        }
    }
}

// ------------------------- KV reduction (SIMT, fp32) ------------------------
// 256 threads: each owns 2 consecutive m and 32 dk -> 64 FMA per t per thread.
__global__ __launch_bounds__(256) void kv_kernel()
{
    __shared__ float Vs[16][64];
    const int bh    = blockIdx.x;
    const int chunk = blockIdx.y;
    const int tid   = threadIdx.x;
    const int mp    = (tid & 127) * 2;
    const int half  = tid >> 7;
    const int d0    = half * 32;

    float acc0[32], acc1[32];
#pragma unroll
    for (int j = 0; j < 32; j++) { acc0[j] = 0.0f; acc1[j] = 0.0f; }
    float ks0 = 0.0f, ks1 = 0.0f;

    const int TCH = Tc / NCHUNK;    // 128
    const int t0 = chunk * TCH;
    const float* Vb = g_V + (size_t)bh * Tc * DKc;
    const float* Pb = g_phiK + (size_t)bh * Tc * Mc;

    for (int tt0 = t0; tt0 < t0 + TCH; tt0 += 16) {
        __syncthreads();
        for (int i = tid; i < 16 * 64; i += 256)
            ((float*)Vs)[i] = Vb[(size_t)tt0 * 64 + i];
        __syncthreads();
#pragma unroll
        for (int tt = 0; tt < 16; tt++) {
            float2 p = *(const float2*)(Pb + (size_t)(tt0 + tt) * Mc + mp);
            ks0 += p.x; ks1 += p.y;
            const float4* v4 = (const float4*)(&Vs[tt][d0]);
#pragma unroll
            for (int q = 0; q < 8; q++) {
                float4 v = v4[q];
                acc0[q*4+0] += p.x * v.x; acc1[q*4+0] += p.y * v.x;
                acc0[q*4+1] += p.x * v.y; acc1[q*4+1] += p.y * v.y;
                acc0[q*4+2] += p.x * v.z; acc1[q*4+2] += p.y * v.z;
                acc0[q*4+3] += p.x * v.w; acc1[q*4+3] += p.y * v.w;
            }
        }
    }

    float* o = g_KVp + ((size_t)chunk * BHc + bh) * (Mc * DKc) + mp * DKc + d0;
#pragma unroll
    for (int j = 0; j < 32; j++) o[j] = acc0[j];
    o += DKc;
#pragma unroll
    for (int j = 0; j < 32; j++) o[j] = acc1[j];
    if (half == 0) {
        g_Ksp[((size_t)chunk * BHc + bh) * Mc + mp]     = ks0;
        g_Ksp[((size_t)chunk * BHc + bh) * Mc + mp + 1] = ks1;
    }
}

// Reduce partials -> KVaug [bh][72][256] bf16 hi/lo.
__global__ __launch_bounds__(256) void kv_reduce()
{
    int i = blockIdx.x * 256 + threadIdx.x;
    if (i < BHc * Mc * DKc) {
        float s = 0.0f;
#pragma unroll
        for (int c = 0; c < NCHUNK; c++) s += g_KVp[(size_t)c * (BHc * Mc * DKc) + i];
        int bh = i >> 14, rem = i & 16383, m = rem >> 6, dd = rem & 63;
        size_t o = ((size_t)bh * NAUG + dd) * Mc + m;
        __nv_bfloat16 hi = __float2bfloat16(s);
        g_kvh[o] = hi;
        g_kvl[o] = __float2bfloat16(s - __bfloat162float(hi));
    }
    if (i < BHc * Mc) {
        float s = 0.0f;
#pragma unroll
        for (int c = 0; c < NCHUNK; c++) s += g_Ksp[c * (BHc * Mc) + i];
        int bh = i >> 8, m = i & 255;
        size_t o = ((size_t)bh * NAUG + 64) * Mc + m;
        __nv_bfloat16 hi = __float2bfloat16(s);
        g_kvh[o] = hi;
        g_kvl[o] = __float2bfloat16(s - __bfloat162float(hi));
    }
    if (i < BHc * 7 * Mc) {
        int bh = i / (7 * Mc), r = i % (7 * Mc);
        size_t o = ((size_t)bh * NAUG + 65 + r / Mc) * Mc + (r % Mc);
        g_kvh[o] = __float2bfloat16(0.0f);
        g_kvl[o] = __float2bfloat16(0.0f);
    }
}

// ---------------------------------------------------------------------------
// num via mma: out[128t x 72] = phiQ[128 x 256] @ KVaug[72 x 256]^T.
// Col 64 = den. Epilogue divides, writes merged as bf16 hi/lo.
// ---------------------------------------------------------------------------
#define NUM_STAGE 53248
__global__ __launch_bounds__(256, 1) void num_mma()
{
    extern __shared__ char smem[];
    const uint32_t sbase = smem_u32(smem);
    const int tid = threadIdx.x, wid = tid >> 5, lane = tid & 31;
    const int bh = blockIdx.x, tile = blockIdx.y;
    const int b = bh >> 4, h = bh & (Hc - 1);

    // zero B rows 72-79 in both stages/buffers
    {
        int g = tid;
        int stg = g >> 7, rem = g & 127, buf = rem >> 6, c = rem & 63;
        uint32_t off = (uint32_t)(stg * NUM_STAGE + 32768 + buf * 10240 + 9216 + c * 16);
        *(uint4*)(smem + off) = make_uint4(0, 0, 0, 0);
    }

    const size_t abase = ((size_t)bh * Tc + tile * 128) * Mc;
    const size_t bbase = (size_t)bh * NAUG * Mc;

    auto load_stage = [&](int c, int buf) {
        uint32_t st = sbase + (uint32_t)buf * NUM_STAGE;
        int k0 = c * 64;
        cpa_g<256>(g_pQh + abase + k0, Mc, st,          tid, 1024);
        cpa_g<256>(g_pQl + abase + k0, Mc, st + 16384,  tid, 1024);
        cpa_g<256>(g_kvh + bbase + k0, Mc, st + 32768,  tid, 576);
        cpa_g<256>(g_kvl + bbase + k0, Mc, st + 43008,  tid, 576);
        CPA_COMMIT();
    };

    float acc[9][4];
#pragma unroll
    for (int nb = 0; nb < 9; nb++)
#pragma unroll
        for (int j = 0; j < 4; j++) acc[nb][j] = 0.0f;

    const int m0 = wid * 16;
    const uint32_t arow = (uint32_t)(m0 + (lane & 15));
    const uint32_t akh  = (uint32_t)((lane >> 4) << 3);
    const uint32_t brw  = (uint32_t)(((lane >> 4) << 3) + (lane & 7));
    const uint32_t bkh  = (uint32_t)(lane & 8);

    load_stage(0, 0);

    for (int c = 0; c < 4; c++) {
        if (c + 1 < 4) { load_stage(c + 1, (c + 1) & 1); CPA_WAIT(1); }
        else           { CPA_WAIT(0); }
        __syncthreads();

        const uint32_t st = sbase + (uint32_t)(c & 1) * NUM_STAGE;
#pragma unroll
        for (int ks = 0; ks < 4; ks++) {
            uint32_t ah[4], al[4];
            uint32_t aoff = swz_b(arow * 128 + (ks * 16 + akh) * 2);
            ldsm_x4(ah, st + aoff);
            ldsm_x4(al, st + 16384 + aoff);
            uint32_t b4h[5][4], b4l[5][4];
#pragma unroll
            for (int nb2 = 0; nb2 < 5; nb2++) {
                uint32_t boff = swz_b((nb2 * 16 + brw) * 128 + (ks * 16 + bkh) * 2);
                ldsm_x4(b4h[nb2], st + 32768 + boff);
                ldsm_x4(b4l[nb2], st + 43008 + boff);
            }
            // pass-major over 9 accumulators
#pragma unroll
            for (int nb = 0; nb < 9; nb++)
                mma_bf16(acc[nb], ah, &b4h[nb >> 1][(nb & 1) * 2]);
#pragma unroll
            for (int nb = 0; nb < 9; nb++)
                mma_bf16(acc[nb], ah, &b4l[nb >> 1][(nb & 1) * 2]);
#pragma unroll
            for (int nb = 0; nb < 9; nb++)
                mma_bf16(acc[nb], al, &b4h[nb >> 1][(nb & 1) * 2]);
        }
        __syncthreads();
    }

    const int group = lane >> 2, tig = lane & 3;
    float den0 = __shfl_sync(0xffffffffu, acc[8][0], lane & ~3);
    float den1 = __shfl_sync(0xffffffffu, acc[8][2], lane & ~3);
    float inv0 = 1.0f / (den0 + EPSc);
    float inv1 = 1.0f / (den1 + EPSc);

    const int t0 = tile * 128 + m0 + group;
    const size_t row0 = (size_t)(b * Tc + t0) * Dc + h * DKc;
    const size_t row1 = row0 + (size_t)8 * Dc;
#pragma unroll
    for (int nb = 0; nb < 8; nb++) {
        int col = nb * 8 + tig * 2;
        split_store(g_mhi, g_mlo, row0 + col, acc[nb][0] * inv0, acc[nb][1] * inv0);
        split_store(g_mhi, g_mlo, row1 + col, acc[nb][2] * inv1, acc[nb][3] * inv1);
    }
}

// ------------------------- launch ------------------------------------------
extern "C" void kernel_launch(void* const* d_in, const int* in_sizes, int n_in,
                              void* d_out, int out_size)
{
    const float* x    = (const float*)d_in[0];
    const float* Wq   = (const float*)d_in[1];
    const float* Wk   = (const float*)d_in[2];
    const float* Wv   = (const float*)d_in[3];
    const float* Wo   = (const float*)d_in[4];
    const float* bo   = (const float*)d_in[5];
    const float* proj = (const float*)d_in[6];
    float* out = (float*)d_out;

    __nv_bfloat16 *xhi, *xlo, *mhi, *mlo, *ph, *pl;
    __nv_bfloat16 *wqh, *wql, *wkh, *wkl, *wvh, *wvl, *woh, *wol;
    cudaGetSymbolAddress((void**)&xhi, g_xhi); cudaGetSymbolAddress((void**)&xlo, g_xlo);
    cudaGetSymbolAddress((void**)&mhi, g_mhi); cudaGetSymbolAddress((void**)&mlo, g_mlo);
    cudaGetSymbolAddress((void**)&ph,  g_ph);  cudaGetSymbolAddress((void**)&pl,  g_pl);
    cudaGetSymbolAddress((void**)&wqh, g_wqh); cudaGetSymbolAddress((void**)&wql, g_wql);
    cudaGetSymbolAddress((void**)&wkh, g_wkh); cudaGetSymbolAddress((void**)&wkl, g_wkl);
    cudaGetSymbolAddress((void**)&wvh, g_wvh); cudaGetSymbolAddress((void**)&wvl, g_wvl);
    cudaGetSymbolAddress((void**)&woh, g_woh); cudaGetSymbolAddress((void**)&wol, g_wol);

    const int GEMM_SMEM = 2 * GSTAGE;     // 96 KB -> 2 CTAs/SM
    const int PHI_SMEM  = 98304;          // 96 KB
    const int NUM_SMEM  = 2 * NUM_STAGE;  // 104 KB
    cudaFuncSetAttribute(tc_gemm<0>, cudaFuncAttributeMaxDynamicSharedMemorySize, GEMM_SMEM);
    cudaFuncSetAttribute(tc_gemm<1>, cudaFuncAttributeMaxDynamicSharedMemorySize, GEMM_SMEM);
    cudaFuncSetAttribute(phi_mma,    cudaFuncAttributeMaxDynamicSharedMemorySize, PHI_SMEM);
    cudaFuncSetAttribute(num_mma,    cudaFuncAttributeMaxDynamicSharedMemorySize, NUM_SMEM);

    // 0) split fp32 operands into bf16 hi/lo
    split_kernel<<<(BTc * Dc / 4 + 255) / 256, 256>>>(x, xhi, xlo, BTc * Dc / 4);
    wsplit_kernel<<<dim3((Dc * Dc / 4 + 255) / 256, 4), 256>>>(
        Wq, Wk, Wv, Wo, wqh, wql, wkh, wkl, wvh, wvl, woh, wol);
    split_kernel<<<(Hc * Mc * DKc / 4 + 255) / 256, 256>>>(proj, ph, pl, Hc * Mc * DKc / 4);

    // 1) Q/K/V projections (Q/K -> bf16 hi/lo head-transposed; V -> fp32)
    tc_gemm<0><<<dim3(Dc / 128, BTc / 64, 3), 256, GEMM_SMEM>>>(
        xhi, xlo, wqh, wql, wkh, wkl, wvh, wvl, nullptr, nullptr);

    // 2) FAVOR+ features on tensor cores
    phi_mma<<<dim3(BHc, Tc / 128, 2), 256, PHI_SMEM>>>();

    // 3) KV/Ksum reduction over T -> KVaug bf16 hi/lo
    kv_kernel<<<dim3(BHc, NCHUNK), 256>>>();
    kv_reduce<<<(BHc * Mc * DKc + 255) / 256, 256>>>();

    // 4) numerator/denominator on tensor cores -> merged bf16 hi/lo
    num_mma<<<dim3(BHc, Tc / 128), 256, NUM_SMEM>>>();

    // 5) output projection
    tc_gemm<1><<<dim3(Dc / 128, BTc / 64, 1), 256, GEMM_SMEM>>>(
        mhi, mlo, woh, wol, nullptr, nullptr, nullptr, nullptr, bo, out);
}

// round 16
// speedup vs baseline: 1.1843x; 1.1843x over previous
#include <cuda_runtime.h>
#include <cuda_bf16.h>
#include <cstdint>

// ---------------------------------------------------------------------------
// FAVOR+ (Performer) attention. Shapes: B=2, T=4096, d=1024, h=16, m=256, dk=64.
// All GEMM-shaped stages incl. the KV reduction on mma.sync bf16 split-x3.
// ---------------------------------------------------------------------------

#define Bc   2
#define Hc   16
#define Tc   4096
#define DKc  64
#define Mc   256
#define Dc   1024
#define BHc  (Bc*Hc)     // 32
#define BTc  (Bc*Tc)     // 8192
#define KVCH   16        // K-chunks for kv_mma
#define KSTILE 32        // phi tiles contributing Ksum partials (Tc/128)
#define NAUG 72          // KV cols (64) + Ksum col + pad to mult of 8

#define EPSc        1e-6f
#define INV_SQRT_M  0.0625f
#define INV_SQRT_DK 0.125f

// ------------------------- device scratch ----------------------------------
__device__ float g_KVp [KVCH*BHc*Mc*DKc];
__device__ float g_Ksp [KSTILE*BHc*Mc];

__device__ __align__(16) __nv_bfloat16 g_Qh[BHc*Tc*DKc], g_Ql[BHc*Tc*DKc];
__device__ __align__(16) __nv_bfloat16 g_Kh[BHc*Tc*DKc], g_Kl[BHc*Tc*DKc];
__device__ __align__(16) __nv_bfloat16 g_Vh[BHc*Tc*DKc], g_Vl[BHc*Tc*DKc];
__device__ __align__(16) __nv_bfloat16 g_pQh[BHc*Tc*Mc], g_pQl[BHc*Tc*Mc];
__device__ __align__(16) __nv_bfloat16 g_pKh[BHc*Tc*Mc], g_pKl[BHc*Tc*Mc];
__device__ __align__(16) __nv_bfloat16 g_kvh[BHc*NAUG*Mc], g_kvl[BHc*NAUG*Mc];
__device__ __align__(16) __nv_bfloat16 g_ph[Hc*Mc*DKc],  g_pl[Hc*Mc*DKc];

__device__ __align__(16) __nv_bfloat16 g_xhi[BTc*Dc],  g_xlo[BTc*Dc];
__device__ __align__(16) __nv_bfloat16 g_mhi[BTc*Dc],  g_mlo[BTc*Dc];
__device__ __align__(16) __nv_bfloat16 g_wqh[Dc*Dc], g_wql[Dc*Dc];
__device__ __align__(16) __nv_bfloat16 g_wkh[Dc*Dc], g_wkl[Dc*Dc];
__device__ __align__(16) __nv_bfloat16 g_wvh[Dc*Dc], g_wvl[Dc*Dc];
__device__ __align__(16) __nv_bfloat16 g_woh[Dc*Dc], g_wol[Dc*Dc];

// ------------------------- helpers -----------------------------------------
__device__ __forceinline__ uint32_t smem_u32(const void* p) {
    uint32_t a;
    asm("{ .reg .u64 t; cvta.to.shared.u64 t, %1; cvt.u32.u64 %0, t; }"
        : "=r"(a) : "l"(p));
    return a;
}

// swizzle for 128B-pitch tiles
__device__ __forceinline__ uint32_t swz_b(uint32_t off) {
    return off ^ ((off >> 3) & 0x70);
}
// swizzle for 512B-pitch tiles (rows of 256 bf16)
__device__ __forceinline__ uint32_t swz512(uint32_t off) {
    return off ^ ((off >> 5) & 0x70);
}

__device__ __forceinline__ void ldsm_x4(uint32_t* r, uint32_t addr) {
    asm volatile("ldmatrix.sync.aligned.m8n8.x4.shared.b16 {%0,%1,%2,%3}, [%4];"
                 : "=r"(r[0]), "=r"(r[1]), "=r"(r[2]), "=r"(r[3]) : "r"(addr));
}
__device__ __forceinline__ void ldsm_x4_t(uint32_t* r, uint32_t addr) {
    asm volatile("ldmatrix.sync.aligned.m8n8.x4.trans.shared.b16 {%0,%1,%2,%3}, [%4];"
                 : "=r"(r[0]), "=r"(r[1]), "=r"(r[2]), "=r"(r[3]) : "r"(addr));
}

__device__ __forceinline__ void mma_bf16(float* d, const uint32_t* a, const uint32_t* b) {
    asm volatile(
        "mma.sync.aligned.m16n8k16.row.col.f32.bf16.bf16.f32 "
        "{%0,%1,%2,%3}, {%4,%5,%6,%7}, {%8,%9}, {%0,%1,%2,%3};"
        : "+f"(d[0]), "+f"(d[1]), "+f"(d[2]), "+f"(d[3])
        : "r"(a[0]), "r"(a[1]), "r"(a[2]), "r"(a[3]), "r"(b[0]), "r"(b[1]));
}

__device__ __forceinline__ void split_store(__nv_bfloat16* hp, __nv_bfloat16* lp,
                                            size_t idx, float a, float b) {
    __nv_bfloat16 ha = __float2bfloat16(a), hb = __float2bfloat16(b);
    __nv_bfloat16 la = __float2bfloat16(a - __bfloat162float(ha));
    __nv_bfloat16 lb = __float2bfloat16(b - __bfloat162float(hb));
    *(__nv_bfloat162*)(hp + idx) = __nv_bfloat162{ha, hb};
    *(__nv_bfloat162*)(lp + idx) = __nv_bfloat162{la, lb};
}

// cp.async rows of 64 bf16 (128B) into swizzled smem tile.
template <int NT>
__device__ __forceinline__ void cpa_g(const __nv_bfloat16* __restrict__ src, int ldk,
                                      uint32_t dst, int tid, int nchunks) {
    for (int g = tid; g < nchunks; g += NT) {
        int row = g >> 3, cg = g & 7;
        const void* gp = src + (size_t)row * ldk + cg * 8;
        uint32_t d = dst + swz_b((uint32_t)(row * 128 + cg * 16));
        asm volatile("cp.async.cg.shared.global [%0], [%1], 16;"
                     :: "r"(d), "l"(gp) : "memory");
    }
}

// cp.async rows of 256 bf16 (512B) into swz512 smem tile.
template <int NT>
__device__ __forceinline__ void cpa512(const __nv_bfloat16* __restrict__ src, int ldk,
                                       uint32_t dst, int tid, int nchunks) {
    for (int g = tid; g < nchunks; g += NT) {
        int row = g >> 5, cg = g & 31;
        const void* gp = src + (size_t)row * ldk + cg * 8;
        uint32_t d = dst + swz512((uint32_t)(row * 512 + cg * 16));
        asm volatile("cp.async.cg.shared.global [%0], [%1], 16;"
                     :: "r"(d), "l"(gp) : "memory");
    }
}

#define CPA_COMMIT() asm volatile("cp.async.commit_group;" ::: "memory")
#define CPA_WAIT(n)  asm volatile("cp.async.wait_group %0;" :: "n"(n) : "memory")

// ------------------------- split fp32 -> bf16 hi/lo ------------------------
__device__ __forceinline__ void split_body(const float* __restrict__ src,
                                           __nv_bfloat16* __restrict__ hi,
                                           __nv_bfloat16* __restrict__ lo, int i)
{
    float4 v = ((const float4*)src)[i];
    __nv_bfloat16 h0 = __float2bfloat16(v.x);
    __nv_bfloat16 h1 = __float2bfloat16(v.y);
    __nv_bfloat16 h2 = __float2bfloat16(v.z);
    __nv_bfloat16 h3 = __float2bfloat16(v.w);
    __nv_bfloat16 l0 = __float2bfloat16(v.x - __bfloat162float(h0));
    __nv_bfloat16 l1 = __float2bfloat16(v.y - __bfloat162float(h1));
    __nv_bfloat16 l2 = __float2bfloat16(v.z - __bfloat162float(h2));
    __nv_bfloat16 l3 = __float2bfloat16(v.w - __bfloat162float(h3));
    __nv_bfloat162* hp = (__nv_bfloat162*)hi;
    __nv_bfloat162* lp = (__nv_bfloat162*)lo;
    hp[2*i]   = __nv_bfloat162{h0, h1};
    hp[2*i+1] = __nv_bfloat162{h2, h3};
    lp[2*i]   = __nv_bfloat162{l0, l1};
    lp[2*i+1] = __nv_bfloat162{l2, l3};
}

__global__ __launch_bounds__(256) void split_kernel(const float* __restrict__ src,
                                                    __nv_bfloat16* __restrict__ hi,
                                                    __nv_bfloat16* __restrict__ lo,
                                                    int n4)
{
    int i = blockIdx.x * 256 + threadIdx.x;
    if (i < n4) split_body(src, hi, lo, i);
}

__global__ __launch_bounds__(256) void wsplit_kernel(
    const float* __restrict__ s0, const float* __restrict__ s1,
    const float* __restrict__ s2, const float* __restrict__ s3,
    __nv_bfloat16* h0, __nv_bfloat16* l0, __nv_bfloat16* h1, __nv_bfloat16* l1,
    __nv_bfloat16* h2, __nv_bfloat16* l2, __nv_bfloat16* h3, __nv_bfloat16* l3)
{
    int i = blockIdx.x * 256 + threadIdx.x;
    if (i >= Dc * Dc / 4) return;
    int z = blockIdx.y;
    const float* s = (z == 0) ? s0 : (z == 1) ? s1 : (z == 2) ? s2 : s3;
    __nv_bfloat16* h = (z == 0) ? h0 : (z == 1) ? h1 : (z == 2) ? h2 : h3;
    __nv_bfloat16* l = (z == 0) ? l0 : (z == 1) ? l1 : (z == 2) ? l2 : l3;
    split_body(s, h, l, i);
}

// ---------------------------------------------------------------------------
// Big GEMM: C[M,N] = A[M,K] @ W[N,K]^T, K = 1024, bf16 split-x3.
// CTA 64x128, 2-stage 96KB -> 2 CTAs/SM. 8 warps, warp tile 32x32.
// MODE 0: z picks Wq/Wk/Wv; writes bf16 hi/lo head-transposed (Q,K scaled).
// MODE 1: Wo + bias -> plain [BT,D] fp32 to d_out.
// ---------------------------------------------------------------------------
#define GSTAGE 49152
template <int MODE>
__global__ __launch_bounds__(256, 2) void tc_gemm(
    const __nv_bfloat16* __restrict__ Ahi, const __nv_bfloat16* __restrict__ Alo,
    const __nv_bfloat16* __restrict__ W0h, const __nv_bfloat16* __restrict__ W0l,
    const __nv_bfloat16* __restrict__ W1h, const __nv_bfloat16* __restrict__ W1l,
    const __nv_bfloat16* __restrict__ W2h, const __nv_bfloat16* __restrict__ W2l,
    const float* __restrict__ bias, float* __restrict__ Oplain)
{
    extern __shared__ char smem[];
    const uint32_t sbase = smem_u32(smem);
    const int tid = threadIdx.x, wid = tid >> 5, lane = tid & 31;
    const int bn = blockIdx.x * 128, bm = blockIdx.y * 64;
    const int z = (MODE == 0) ? blockIdx.z : 0;

    const __nv_bfloat16 *Bh, *Bl;
    float scale = 1.0f;
    if (MODE == 0) {
        Bh = (z == 0) ? W0h : ((z == 1) ? W1h : W2h);
        Bl = (z == 0) ? W0l : ((z == 1) ? W1l : W2l);
        scale = (z < 2) ? INV_SQRT_DK : 1.0f;
    } else {
        Bh = W0h; Bl = W0l;
    }

    auto load_stage = [&](int c, int stg) {
        uint32_t st = sbase + (uint32_t)stg * (uint32_t)GSTAGE;
        int k0 = c * 64;
        cpa_g<256>(Ahi + (size_t)bm * Dc + k0, Dc, st,          tid, 512);
        cpa_g<256>(Alo + (size_t)bm * Dc + k0, Dc, st + 8192,   tid, 512);
        cpa_g<256>(Bh  + (size_t)bn * Dc + k0, Dc, st + 16384,  tid, 1024);
        cpa_g<256>(Bl  + (size_t)bn * Dc + k0, Dc, st + 32768,  tid, 1024);
        CPA_COMMIT();
    };

    float acc[2][4][4];
#pragma unroll
    for (int a = 0; a < 2; a++)
#pragma unroll
        for (int b = 0; b < 4; b++)
#pragma unroll
            for (int c = 0; c < 4; c++) acc[a][b][c] = 0.0f;

    const int wm = wid & 1, wn = wid >> 1;
    const uint32_t arow = (uint32_t)(wm * 32 + (lane & 15));
    const uint32_t akh  = (uint32_t)((lane >> 4) << 3);
    const uint32_t brow = (uint32_t)(wn * 32 + ((lane >> 4) << 3) + (lane & 7));
    const uint32_t bkh  = (uint32_t)(lane & 8);

    load_stage(0, 0);

    for (int c = 0; c < 16; c++) {
        if (c + 1 < 16) { load_stage(c + 1, (c + 1) & 1); CPA_WAIT(1); }
        else            { CPA_WAIT(0); }
        __syncthreads();

        const uint32_t st = sbase + (uint32_t)(c & 1) * (uint32_t)GSTAGE;
#pragma unroll
        for (int ks = 0; ks < 4; ks++) {
            uint32_t ah[2][4], al[2][4], bhf[2][4], blf[2][4];
#pragma unroll
            for (int mb = 0; mb < 2; mb++) {
                uint32_t off = swz_b((arow + mb * 16) * 128 + (ks * 16 + akh) * 2);
                ldsm_x4(ah[mb], st + off);
                ldsm_x4(al[mb], st + 8192 + off);
            }
#pragma unroll
            for (int nb2 = 0; nb2 < 2; nb2++) {
                uint32_t off = swz_b((brow + nb2 * 16) * 128 + (ks * 16 + bkh) * 2);
                ldsm_x4(bhf[nb2], st + 16384 + off);
                ldsm_x4(blf[nb2], st + 32768 + off);
            }
#pragma unroll
            for (int mb = 0; mb < 2; mb++)
#pragma unroll
                for (int nb = 0; nb < 4; nb++)
                    mma_bf16(acc[mb][nb], ah[mb], &bhf[nb >> 1][(nb & 1) * 2]);
#pragma unroll
            for (int mb = 0; mb < 2; mb++)
#pragma unroll
                for (int nb = 0; nb < 4; nb++)
                    mma_bf16(acc[mb][nb], ah[mb], &blf[nb >> 1][(nb & 1) * 2]);
#pragma unroll
            for (int mb = 0; mb < 2; mb++)
#pragma unroll
                for (int nb = 0; nb < 4; nb++)
                    mma_bf16(acc[mb][nb], al[mb], &bhf[nb >> 1][(nb & 1) * 2]);
        }
        __syncthreads();
    }

    // ---- epilogue ----
    const int group = lane >> 2, tig = lane & 3;
#pragma unroll
    for (int mb = 0; mb < 2; mb++) {
        int m0 = bm + wm * 32 + mb * 16 + group;
#pragma unroll
        for (int nb = 0; nb < 4; nb++) {
            int n0 = bn + wn * 32 + nb * 8 + tig * 2;
            float* d = acc[mb][nb];
            if (MODE == 0) {
                int head = n0 >> 6, dd = n0 & 63;
                int bb = m0 >> 12, t = m0 & (Tc - 1);
                size_t base = ((((size_t)bb * Hc + head) * Tc) + t) * DKc + dd;
                __nv_bfloat16* qh = (z == 0) ? g_Qh : ((z == 1) ? g_Kh : g_Vh);
                __nv_bfloat16* ql = (z == 0) ? g_Ql : ((z == 1) ? g_Kl : g_Vl);
                split_store(qh, ql, base,           d[0] * scale, d[1] * scale);
                split_store(qh, ql, base + 8 * DKc, d[2] * scale, d[3] * scale);
            } else {
                float2 bv = *(const float2*)(bias + n0);
                float* o = Oplain + (size_t)m0 * Dc + n0;
                *(float2*)o           = make_float2(d[0] + bv.x, d[1] + bv.y);
                *(float2*)(o + 8*Dc)  = make_float2(d[2] + bv.x, d[3] + bv.y);
            }
        }
    }
}

// ---------------------------------------------------------------------------
// phi via mma: xw[128t x 256m] = X[128 x 64] @ proj[256 x 64]^T (split-x3),
// then rowmax/exp epilogue. z=0: Q -> phiQ hi/lo. z=1: K -> phiK hi/lo +
// per-tile column sums (Ksum partials, fp32, deterministic tree).
// smem: Ahi 16K | Alo 16K | Bhi 32K | Blo 32K | sKs 8K = 104.5K.
// ---------------------------------------------------------------------------
#define PHI_SMEM (98304 + 8192)
__global__ __launch_bounds__(256, 1) void phi_mma()
{
    extern __shared__ char smem[];
    const uint32_t sbase = smem_u32(smem);
    float* sKs = (float*)(smem + 98304);
    const int tid = threadIdx.x, wid = tid >> 5, lane = tid & 31;
    const int bh = blockIdx.x, tile = blockIdx.y, z = blockIdx.z;
    const int h = bh & (Hc - 1);

    const __nv_bfloat16* Ah = z ? g_Kh : g_Qh;
    const __nv_bfloat16* Al = z ? g_Kl : g_Ql;

    const size_t abase = ((size_t)bh * Tc + tile * 128) * DKc;
    cpa_g<256>(Ah + abase, DKc, sbase,         tid, 1024);
    cpa_g<256>(Al + abase, DKc, sbase + 16384, tid, 1024);
    const size_t pbase = (size_t)h * Mc * DKc;
    cpa_g<256>(g_ph + pbase, DKc, sbase + 32768, tid, 2048);
    cpa_g<256>(g_pl + pbase, DKc, sbase + 65536, tid, 2048);
    CPA_COMMIT();
    CPA_WAIT(0);
    __syncthreads();

    float acc[32][4];
#pragma unroll
    for (int nb = 0; nb < 32; nb++)
#pragma unroll
        for (int j = 0; j < 4; j++) acc[nb][j] = 0.0f;

    const int m0 = wid * 16;
    const uint32_t arow = (uint32_t)(m0 + (lane & 15));
    const uint32_t akh  = (uint32_t)((lane >> 4) << 3);
    const uint32_t brw  = (uint32_t)(((lane >> 4) << 3) + (lane & 7));
    const uint32_t bkh  = (uint32_t)(lane & 8);

#pragma unroll
    for (int ks = 0; ks < 4; ks++) {
        uint32_t ah[4], al[4];
        uint32_t aoff = swz_b(arow * 128 + (ks * 16 + akh) * 2);
        ldsm_x4(ah, sbase + aoff);
        ldsm_x4(al, sbase + 16384 + aoff);
#pragma unroll
        for (int nb4 = 0; nb4 < 8; nb4++) {
            uint32_t b4h[2][4], b4l[2][4];
#pragma unroll
            for (int q = 0; q < 2; q++) {
                uint32_t boff = swz_b(((nb4 * 2 + q) * 16 + brw) * 128 + (ks * 16 + bkh) * 2);
                ldsm_x4(b4h[q], sbase + 32768 + boff);
                ldsm_x4(b4l[q], sbase + 65536 + boff);
            }
#pragma unroll
            for (int q = 0; q < 2; q++)
#pragma unroll
                for (int w = 0; w < 2; w++)
                    mma_bf16(acc[(nb4 * 2 + q) * 2 + w], ah, &b4h[q][w * 2]);
#pragma unroll
            for (int q = 0; q < 2; q++)
#pragma unroll
                for (int w = 0; w < 2; w++)
                    mma_bf16(acc[(nb4 * 2 + q) * 2 + w], ah, &b4l[q][w * 2]);
#pragma unroll
            for (int q = 0; q < 2; q++)
#pragma unroll
                for (int w = 0; w < 2; w++)
                    mma_bf16(acc[(nb4 * 2 + q) * 2 + w], al, &b4h[q][w * 2]);
        }
    }

    // ---- epilogue: rowmax, xnorm, exp, store (+Ksum for z=1) ----
    const int group = lane >> 2, tig = lane & 3;
    float mx0 = -1e30f, mx1 = -1e30f;
#pragma unroll
    for (int nb = 0; nb < 32; nb++) {
        mx0 = fmaxf(mx0, fmaxf(acc[nb][0], acc[nb][1]));
        mx1 = fmaxf(mx1, fmaxf(acc[nb][2], acc[nb][3]));
    }
#pragma unroll
    for (int o = 1; o < 4; o <<= 1) {
        mx0 = fmaxf(mx0, __shfl_xor_sync(0xffffffffu, mx0, o));
        mx1 = fmaxf(mx1, __shfl_xor_sync(0xffffffffu, mx1, o));
    }

    auto rowsq = [&](int r) -> float {
        float s = 0.0f;
#pragma unroll
        for (int cg = 0; cg < 8; cg++) {
            uint32_t off = swz_b((uint32_t)(r * 128 + cg * 16));
            uint4 hv = *(const uint4*)(smem + off);
            uint4 lv = *(const uint4*)(smem + 16384 + off);
            const __nv_bfloat162* hp = (const __nv_bfloat162*)&hv;
            const __nv_bfloat162* lp = (const __nv_bfloat162*)&lv;
#pragma unroll
            for (int j = 0; j < 4; j++) {
                float2 hf = __bfloat1622float2(hp[j]);
                float2 lf = __bfloat1622float2(lp[j]);
                float a = hf.x + lf.x, b = hf.y + lf.y;
                s += a * a + b * b;
            }
        }
        return s;
    };
    const int r0l = m0 + group, r1l = r0l + 8;
    float e0 = expf(-0.5f * rowsq(r0l));
    float e1 = expf(-0.5f * rowsq(r1l));

    __nv_bfloat16* ph = z ? g_pKh : g_pQh;
    __nv_bfloat16* pl = z ? g_pKl : g_pQl;
    const size_t idx0 = ((size_t)bh * Tc + tile * 128 + r0l) * Mc;
    const size_t idx1 = ((size_t)bh * Tc + tile * 128 + r1l) * Mc;
#pragma unroll
    for (int nb = 0; nb < 32; nb++) {
        int col = nb * 8 + tig * 2;
        float v00 = (expf(acc[nb][0] - mx0) * e0 + EPSc) * INV_SQRT_M;
        float v01 = (expf(acc[nb][1] - mx0) * e0 + EPSc) * INV_SQRT_M;
        float v10 = (expf(acc[nb][2] - mx1) * e1 + EPSc) * INV_SQRT_M;
        float v11 = (expf(acc[nb][3] - mx1) * e1 + EPSc) * INV_SQRT_M;
        split_store(ph, pl, idx0 + col, v00, v01);
        split_store(ph, pl, idx1 + col, v10, v11);
        if (z == 1) {
            float cs0 = v00 + v10, cs1 = v01 + v11;
#pragma unroll
            for (int o = 4; o < 32; o <<= 1) {
                cs0 += __shfl_xor_sync(0xffffffffu, cs0, o);
                cs1 += __shfl_xor_sync(0xffffffffu, cs1, o);
            }
            if (lane < 4) {
                sKs[wid * 256 + nb * 8 + lane * 2]     = cs0;
                sKs[wid * 256 + nb * 8 + lane * 2 + 1] = cs1;
            }
        }
    }
    if (z == 1) {
        __syncthreads();
        float s = 0.0f;
#pragma unroll
        for (int w = 0; w < 8; w++) s += sKs[w * 256 + tid];
        g_Ksp[((size_t)tile * BHc + bh) * Mc + tid] = s;
    }
}

// ---------------------------------------------------------------------------
// kv via mma: KV[m=256, dk=64] = phiK^T[m,t] @ V[t,dk], K=4096 split into
// 16 chunks of 256. Both operands t-major in memory -> ldmatrix.trans frags.
// 8 warps, warp grid 4(M)x2(N), warp tile 64x32, split-x3, fp32 partials.
// smem/stage: Ahi 16K | Alo 16K | Bh 4K | Bl 4K = 40K; 2 stages = 80K.
// ---------------------------------------------------------------------------
#define KVSTAGE 40960
__global__ __launch_bounds__(256, 2) void kv_mma()
{
    extern __shared__ char smem[];
    const uint32_t sbase = smem_u32(smem);
    const int tid = threadIdx.x, wid = tid >> 5, lane = tid & 31;
    const int bh = blockIdx.x, chunk = blockIdx.y;
    const int wm = wid & 3, wn = wid >> 2;

    const size_t pbase = ((size_t)bh * Tc + chunk * 256) * Mc;
    const size_t vbase = ((size_t)bh * Tc + chunk * 256) * DKc;

    auto load_stage = [&](int s, int stg) {
        uint32_t st = sbase + (uint32_t)stg * (uint32_t)KVSTAGE;
        cpa512<256>(g_pKh + pbase + (size_t)s * 32 * Mc, Mc, st,          tid, 1024);
        cpa512<256>(g_pKl + pbase + (size_t)s * 32 * Mc, Mc, st + 16384, tid, 1024);
        cpa_g<256>(g_Vh + vbase + (size_t)s * 32 * DKc, DKc, st + 32768, tid, 256);
        cpa_g<256>(g_Vl + vbase + (size_t)s * 32 * DKc, DKc, st + 36864, tid, 256);
        CPA_COMMIT();
    };

    float acc[4][4][4];
#pragma unroll
    for (int a = 0; a < 4; a++)
#pragma unroll
        for (int b = 0; b < 4; b++)
#pragma unroll
            for (int c = 0; c < 4; c++) acc[a][b][c] = 0.0f;

    // trans-frag lane addressing
    const int krA = ((lane >> 4) & 1) * 8 + (lane & 7);   // + kk
    const int mA  = ((lane >> 3) & 1) * 8;                // + m-tile base
    const int krB = ((lane >> 3) & 1) * 8 + (lane & 7);
    const int nB  = ((lane >> 4) & 1) * 8;

    load_stage(0, 0);

    for (int s = 0; s < 8; s++) {
        if (s + 1 < 8) { load_stage(s + 1, (s + 1) & 1); CPA_WAIT(1); }
        else           { CPA_WAIT(0); }
        __syncthreads();

        const uint32_t st = sbase + (uint32_t)(s & 1) * (uint32_t)KVSTAGE;
#pragma unroll
        for (int kk = 0; kk < 32; kk += 16) {
            uint32_t ah[4][4], al[4][4], bhf[2][4], blf[2][4];
#pragma unroll
            for (int mb = 0; mb < 4; mb++) {
                int mc = wm * 64 + mb * 16 + mA;
                uint32_t off = swz512((uint32_t)((kk + krA) * 512 + mc * 2));
                ldsm_x4_t(ah[mb], st + off);
                ldsm_x4_t(al[mb], st + 16384 + off);
            }
#pragma unroll
            for (int nb2 = 0; nb2 < 2; nb2++) {
                int nc = wn * 32 + nb2 * 16 + nB;
                uint32_t off = swz_b((uint32_t)((kk + krB) * 128 + nc * 2));
                ldsm_x4_t(bhf[nb2], st + 32768 + off);
                ldsm_x4_t(blf[nb2], st + 36864 + off);
            }
#pragma unroll
            for (int mb = 0; mb < 4; mb++)
#pragma unroll
                for (int nb = 0; nb < 4; nb++)
                    mma_bf16(acc[mb][nb], ah[mb], &bhf[nb >> 1][(nb & 1) * 2]);
#pragma unroll
            for (int mb = 0; mb < 4; mb++)
#pragma unroll
                for (int nb = 0; nb < 4; nb++)
                    mma_bf16(acc[mb][nb], ah[mb], &blf[nb >> 1][(nb & 1) * 2]);
#pragma unroll
            for (int mb = 0; mb < 4; mb++)
#pragma unroll
                for (int nb = 0; nb < 4; nb++)
                    mma_bf16(acc[mb][nb], al[mb], &bhf[nb >> 1][(nb & 1) * 2]);
        }
        __syncthreads();
    }

    // ---- partials ----
    const int group = lane >> 2, tig = lane & 3;
    float* o = g_KVp + ((size_t)chunk * BHc + bh) * (Mc * DKc);
#pragma unroll
    for (int mb = 0; mb < 4; mb++) {
        int m0 = wm * 64 + mb * 16 + group;
#pragma unroll
        for (int nb = 0; nb < 4; nb++) {
            int n0 = wn * 32 + nb * 8 + tig * 2;
            float* d = acc[mb][nb];
            *(float2*)(o + (size_t)m0 * DKc + n0)       = make_float2(d[0], d[1]);
            *(float2*)(o + (size_t)(m0 + 8) * DKc + n0) = make_float2(d[2], d[3]);
        }
    }
}

// Reduce partials -> KVaug [bh][72][256] bf16 hi/lo.
__global__ __launch_bounds__(256) void kv_reduce()
{
    int i = blockIdx.x * 256 + threadIdx.x;
    if (i < BHc * Mc * DKc) {
        float s = 0.0f;
#pragma unroll
        for (int c = 0; c < KVCH; c++) s += g_KVp[(size_t)c * (BHc * Mc * DKc) + i];
        int bh = i >> 14, rem = i & 16383, m = rem >> 6, dd = rem & 63;
        size_t o = ((size_t)bh * NAUG + dd) * Mc + m;
        __nv_bfloat16 hi = __float2bfloat16(s);
        g_kvh[o] = hi;
        g_kvl[o] = __float2bfloat16(s - __bfloat162float(hi));
    }
    if (i < BHc * Mc) {
        float s = 0.0f;
#pragma unroll
        for (int c = 0; c < KSTILE; c++) s += g_Ksp[(size_t)c * (BHc * Mc) + i];
        int bh = i >> 8, m = i & 255;
        size_t o = ((size_t)bh * NAUG + 64) * Mc + m;
        __nv_bfloat16 hi = __float2bfloat16(s);
        g_kvh[o] = hi;
        g_kvl[o] = __float2bfloat16(s - __bfloat162float(hi));
    }
    if (i < BHc * 7 * Mc) {
        int bh = i / (7 * Mc), r = i % (7 * Mc);
        size_t o = ((size_t)bh * NAUG + 65 + r / Mc) * Mc + (r % Mc);
        g_kvh[o] = __float2bfloat16(0.0f);
        g_kvl[o] = __float2bfloat16(0.0f);
    }
}

// ---------------------------------------------------------------------------
// num via mma: out[128t x 72] = phiQ[128 x 256] @ KVaug[72 x 256]^T.
// Col 64 = den. Epilogue divides, writes merged as bf16 hi/lo.
// ---------------------------------------------------------------------------
#define NUM_STAGE 53248
__global__ __launch_bounds__(256, 1) void num_mma()
{
    extern __shared__ char smem[];
    const uint32_t sbase = smem_u32(smem);
    const int tid = threadIdx.x, wid = tid >> 5, lane = tid & 31;
    const int bh = blockIdx.x, tile = blockIdx.y;
    const int b = bh >> 4, h = bh & (Hc - 1);

    {
        int g = tid;
        int stg = g >> 7, rem = g & 127, buf = rem >> 6, c = rem & 63;
        uint32_t off = (uint32_t)(stg * NUM_STAGE + 32768 + buf * 10240 + 9216 + c * 16);
        *(uint4*)(smem + off) = make_uint4(0, 0, 0, 0);
    }

    const size_t abase = ((size_t)bh * Tc + tile * 128) * Mc;
    const size_t bbase = (size_t)bh * NAUG * Mc;

    auto load_stage = [&](int c, int buf) {
        uint32_t st = sbase + (uint32_t)buf * NUM_STAGE;
        int k0 = c * 64;
        cpa_g<256>(g_pQh + abase + k0, Mc, st,          tid, 1024);
        cpa_g<256>(g_pQl + abase + k0, Mc, st + 16384,  tid, 1024);
        cpa_g<256>(g_kvh + bbase + k0, Mc, st + 32768,  tid, 576);
        cpa_g<256>(g_kvl + bbase + k0, Mc, st + 43008,  tid, 576);
        CPA_COMMIT();
    };

    float acc[9][4];
#pragma unroll
    for (int nb = 0; nb < 9; nb++)
#pragma unroll
        for (int j = 0; j < 4; j++) acc[nb][j] = 0.0f;

    const int m0 = wid * 16;
    const uint32_t arow = (uint32_t)(m0 + (lane & 15));
    const uint32_t akh  = (uint32_t)((lane >> 4) << 3);
    const uint32_t brw  = (uint32_t)(((lane >> 4) << 3) + (lane & 7));
    const uint32_t bkh  = (uint32_t)(lane & 8);

    load_stage(0, 0);

    for (int c = 0; c < 4; c++) {
        if (c + 1 < 4) { load_stage(c + 1, (c + 1) & 1); CPA_WAIT(1); }
        else           { CPA_WAIT(0); }
        __syncthreads();

        const uint32_t st = sbase + (uint32_t)(c & 1) * NUM_STAGE;
#pragma unroll
        for (int ks = 0; ks < 4; ks++) {
            uint32_t ah[4], al[4];
            uint32_t aoff = swz_b(arow * 128 + (ks * 16 + akh) * 2);
            ldsm_x4(ah, st + aoff);
            ldsm_x4(al, st + 16384 + aoff);
            uint32_t b4h[5][4], b4l[5][4];
#pragma unroll
            for (int nb2 = 0; nb2 < 5; nb2++) {
                uint32_t boff = swz_b((nb2 * 16 + brw) * 128 + (ks * 16 + bkh) * 2);
                ldsm_x4(b4h[nb2], st + 32768 + boff);
                ldsm_x4(b4l[nb2], st + 43008 + boff);
            }
#pragma unroll
            for (int nb = 0; nb < 9; nb++)
                mma_bf16(acc[nb], ah, &b4h[nb >> 1][(nb & 1) * 2]);
#pragma unroll
            for (int nb = 0; nb < 9; nb++)
                mma_bf16(acc[nb], ah, &b4l[nb >> 1][(nb & 1) * 2]);
#pragma unroll
            for (int nb = 0; nb < 9; nb++)
                mma_bf16(acc[nb], al, &b4h[nb >> 1][(nb & 1) * 2]);
        }
        __syncthreads();
    }

    const int group = lane >> 2, tig = lane & 3;
    float den0 = __shfl_sync(0xffffffffu, acc[8][0], lane & ~3);
    float den1 = __shfl_sync(0xffffffffu, acc[8][2], lane & ~3);
    float inv0 = 1.0f / (den0 + EPSc);
    float inv1 = 1.0f / (den1 + EPSc);

    const int t0 = tile * 128 + m0 + group;
    const size_t row0 = (size_t)(b * Tc + t0) * Dc + h * DKc;
    const size_t row1 = row0 + (size_t)8 * Dc;
#pragma unroll
    for (int nb = 0; nb < 8; nb++) {
        int col = nb * 8 + tig * 2;
        split_store(g_mhi, g_mlo, row0 + col, acc[nb][0] * inv0, acc[nb][1] * inv0);
        split_store(g_mhi, g_mlo, row1 + col, acc[nb][2] * inv1, acc[nb][3] * inv1);
    }
}

// ------------------------- launch ------------------------------------------
extern "C" void kernel_launch(void* const* d_in, const int* in_sizes, int n_in,
                              void* d_out, int out_size)
{
    const float* x    = (const float*)d_in[0];
    const float* Wq   = (const float*)d_in[1];
    const float* Wk   = (const float*)d_in[2];
    const float* Wv   = (const float*)d_in[3];
    const float* Wo   = (const float*)d_in[4];
    const float* bo   = (const float*)d_in[5];
    const float* proj = (const float*)d_in[6];
    float* out = (float*)d_out;

    __nv_bfloat16 *xhi, *xlo, *mhi, *mlo, *ph, *pl;
    __nv_bfloat16 *wqh, *wql, *wkh, *wkl, *wvh, *wvl, *woh, *wol;
    cudaGetSymbolAddress((void**)&xhi, g_xhi); cudaGetSymbolAddress((void**)&xlo, g_xlo);
    cudaGetSymbolAddress((void**)&mhi, g_mhi); cudaGetSymbolAddress((void**)&mlo, g_mlo);
    cudaGetSymbolAddress((void**)&ph,  g_ph);  cudaGetSymbolAddress((void**)&pl,  g_pl);
    cudaGetSymbolAddress((void**)&wqh, g_wqh); cudaGetSymbolAddress((void**)&wql, g_wql);
    cudaGetSymbolAddress((void**)&wkh, g_wkh); cudaGetSymbolAddress((void**)&wkl, g_wkl);
    cudaGetSymbolAddress((void**)&wvh, g_wvh); cudaGetSymbolAddress((void**)&wvl, g_wvl);
    cudaGetSymbolAddress((void**)&woh, g_woh); cudaGetSymbolAddress((void**)&wol, g_wol);

    const int GEMM_SMEM = 2 * GSTAGE;     // 96 KB
    const int NUM_SMEM  = 2 * NUM_STAGE;  // 104 KB
    const int KV_SMEM   = 2 * KVSTAGE;    // 80 KB
    cudaFuncSetAttribute(tc_gemm<0>, cudaFuncAttributeMaxDynamicSharedMemorySize, GEMM_SMEM);
    cudaFuncSetAttribute(tc_gemm<1>, cudaFuncAttributeMaxDynamicSharedMemorySize, GEMM_SMEM);
    cudaFuncSetAttribute(phi_mma,    cudaFuncAttributeMaxDynamicSharedMemorySize, PHI_SMEM);
    cudaFuncSetAttribute(kv_mma,     cudaFuncAttributeMaxDynamicSharedMemorySize, KV_SMEM);
    cudaFuncSetAttribute(num_mma,    cudaFuncAttributeMaxDynamicSharedMemorySize, NUM_SMEM);

    // 0) split fp32 operands into bf16 hi/lo
    split_kernel<<<(BTc * Dc / 4 + 255) / 256, 256>>>(x, xhi, xlo, BTc * Dc / 4);
    wsplit_kernel<<<dim3((Dc * Dc / 4 + 255) / 256, 4), 256>>>(
        Wq, Wk, Wv, Wo, wqh, wql, wkh, wkl, wvh, wvl, woh, wol);
    split_kernel<<<(Hc * Mc * DKc / 4 + 255) / 256, 256>>>(proj, ph, pl, Hc * Mc * DKc / 4);

    // 1) Q/K/V projections -> bf16 hi/lo head-transposed (Q,K scaled)
    tc_gemm<0><<<dim3(Dc / 128, BTc / 64, 3), 256, GEMM_SMEM>>>(
        xhi, xlo, wqh, wql, wkh, wkl, wvh, wvl, nullptr, nullptr);

    // 2) FAVOR+ features (phiQ / phiK hi/lo, Ksum partials from z=1)
    phi_mma<<<dim3(BHc, Tc / 128, 2), 256, PHI_SMEM>>>();

    // 3) KV reduction on tensor cores + merge to KVaug
    kv_mma<<<dim3(BHc, KVCH), 256, KV_SMEM>>>();
    kv_reduce<<<(BHc * Mc * DKc + 255) / 256, 256>>>();

    // 4) numerator/denominator -> merged bf16 hi/lo
    num_mma<<<dim3(BHc, Tc / 128), 256, NUM_SMEM>>>();

    // 5) output projection
    tc_gemm<1><<<dim3(Dc / 128, BTc / 64, 1), 256, GEMM_SMEM>>>(
        mhi, mlo, woh, wol, nullptr, nullptr, nullptr, nullptr, bo, out);
}

// round 17
// speedup vs baseline: 1.2305x; 1.0390x over previous
#include <cuda_runtime.h>
#include <cuda_bf16.h>
#include <cstdint>

// ---------------------------------------------------------------------------
// FAVOR+ (Performer) attention. Shapes: B=2, T=4096, d=1024, h=16, m=256, dk=64.
// All GEMM-shaped stages incl. KV reduction on mma.sync bf16 split-x3.
// tc_gemm: 128x128 CTA, 4 warps of 64x64 (LDSM:HMMA=1:6), BK=32 row-paired
// smem layout, 3-stage, 2 CTAs/SM.
// ---------------------------------------------------------------------------

#define Bc   2
#define Hc   16
#define Tc   4096
#define DKc  64
#define Mc   256
#define Dc   1024
#define BHc  (Bc*Hc)     // 32
#define BTc  (Bc*Tc)     // 8192
#define KVCH   16        // K-chunks for kv_mma
#define KSTILE 32        // phi tiles contributing Ksum partials (Tc/128)
#define NAUG 72          // KV cols (64) + Ksum col + pad to mult of 8

#define EPSc        1e-6f
#define INV_SQRT_M  0.0625f
#define INV_SQRT_DK 0.125f

// ------------------------- device scratch ----------------------------------
__device__ float g_KVp [KVCH*BHc*Mc*DKc];
__device__ float g_Ksp [KSTILE*BHc*Mc];

__device__ __align__(16) __nv_bfloat16 g_Qh[BHc*Tc*DKc], g_Ql[BHc*Tc*DKc];
__device__ __align__(16) __nv_bfloat16 g_Kh[BHc*Tc*DKc], g_Kl[BHc*Tc*DKc];
__device__ __align__(16) __nv_bfloat16 g_Vh[BHc*Tc*DKc], g_Vl[BHc*Tc*DKc];
__device__ __align__(16) __nv_bfloat16 g_pQh[BHc*Tc*Mc], g_pQl[BHc*Tc*Mc];
__device__ __align__(16) __nv_bfloat16 g_pKh[BHc*Tc*Mc], g_pKl[BHc*Tc*Mc];
__device__ __align__(16) __nv_bfloat16 g_kvh[BHc*NAUG*Mc], g_kvl[BHc*NAUG*Mc];
__device__ __align__(16) __nv_bfloat16 g_ph[Hc*Mc*DKc],  g_pl[Hc*Mc*DKc];

__device__ __align__(16) __nv_bfloat16 g_xhi[BTc*Dc],  g_xlo[BTc*Dc];
__device__ __align__(16) __nv_bfloat16 g_mhi[BTc*Dc],  g_mlo[BTc*Dc];
__device__ __align__(16) __nv_bfloat16 g_wqh[Dc*Dc], g_wql[Dc*Dc];
__device__ __align__(16) __nv_bfloat16 g_wkh[Dc*Dc], g_wkl[Dc*Dc];
__device__ __align__(16) __nv_bfloat16 g_wvh[Dc*Dc], g_wvl[Dc*Dc];
__device__ __align__(16) __nv_bfloat16 g_woh[Dc*Dc], g_wol[Dc*Dc];

// ------------------------- helpers -----------------------------------------
__device__ __forceinline__ uint32_t smem_u32(const void* p) {
    uint32_t a;
    asm("{ .reg .u64 t; cvta.to.shared.u64 t, %1; cvt.u32.u64 %0, t; }"
        : "=r"(a) : "l"(p));
    return a;
}

// swizzle for 128B-pitch tiles
__device__ __forceinline__ uint32_t swz_b(uint32_t off) {
    return off ^ ((off >> 3) & 0x70);
}
// swizzle for 512B-pitch tiles (rows of 256 bf16)
__device__ __forceinline__ uint32_t swz512(uint32_t off) {
    return off ^ ((off >> 5) & 0x70);
}

__device__ __forceinline__ void ldsm_x4(uint32_t* r, uint32_t addr) {
    asm volatile("ldmatrix.sync.aligned.m8n8.x4.shared.b16 {%0,%1,%2,%3}, [%4];"
                 : "=r"(r[0]), "=r"(r[1]), "=r"(r[2]), "=r"(r[3]) : "r"(addr));
}
__device__ __forceinline__ void ldsm_x4_t(uint32_t* r, uint32_t addr) {
    asm volatile("ldmatrix.sync.aligned.m8n8.x4.trans.shared.b16 {%0,%1,%2,%3}, [%4];"
                 : "=r"(r[0]), "=r"(r[1]), "=r"(r[2]), "=r"(r[3]) : "r"(addr));
}

__device__ __forceinline__ void mma_bf16(float* d, const uint32_t* a, const uint32_t* b) {
    asm volatile(
        "mma.sync.aligned.m16n8k16.row.col.f32.bf16.bf16.f32 "
        "{%0,%1,%2,%3}, {%4,%5,%6,%7}, {%8,%9}, {%0,%1,%2,%3};"
        : "+f"(d[0]), "+f"(d[1]), "+f"(d[2]), "+f"(d[3])
        : "r"(a[0]), "r"(a[1]), "r"(a[2]), "r"(a[3]), "r"(b[0]), "r"(b[1]));
}

__device__ __forceinline__ void split_store(__nv_bfloat16* hp, __nv_bfloat16* lp,
                                            size_t idx, float a, float b) {
    __nv_bfloat16 ha = __float2bfloat16(a), hb = __float2bfloat16(b);
    __nv_bfloat16 la = __float2bfloat16(a - __bfloat162float(ha));
    __nv_bfloat16 lb = __float2bfloat16(b - __bfloat162float(hb));
    *(__nv_bfloat162*)(hp + idx) = __nv_bfloat162{ha, hb};
    *(__nv_bfloat162*)(lp + idx) = __nv_bfloat162{la, lb};
}

// cp.async rows of 64 bf16 (128B) into swizzled smem tile.
template <int NT>
__device__ __forceinline__ void cpa_g(const __nv_bfloat16* __restrict__ src, int ldk,
                                      uint32_t dst, int tid, int nchunks) {
    for (int g = tid; g < nchunks; g += NT) {
        int row = g >> 3, cg = g & 7;
        const void* gp = src + (size_t)row * ldk + cg * 8;
        uint32_t d = dst + swz_b((uint32_t)(row * 128 + cg * 16));
        asm volatile("cp.async.cg.shared.global [%0], [%1], 16;"
                     :: "r"(d), "l"(gp) : "memory");
    }
}

// cp.async rows of 32 bf16 (64B) row-PAIRED into 128B-pitch swizzled tile.
// phys(row,k16) = (row>>1)*128 + (row&1)*64 + k16*16.
template <int NT>
__device__ __forceinline__ void cpa_p(const __nv_bfloat16* __restrict__ src, int ldk,
                                      uint32_t dst, int tid, int nchunks) {
    for (int g = tid; g < nchunks; g += NT) {
        int row = g >> 2, kc = g & 3;
        const void* gp = src + (size_t)row * ldk + kc * 8;
        uint32_t off = (uint32_t)((row >> 1) * 128 + (row & 1) * 64 + kc * 16);
        asm volatile("cp.async.cg.shared.global [%0], [%1], 16;"
                     :: "r"(dst + swz_b(off)), "l"(gp) : "memory");
    }
}

// cp.async rows of 256 bf16 (512B) into swz512 smem tile.
template <int NT>
__device__ __forceinline__ void cpa512(const __nv_bfloat16* __restrict__ src, int ldk,
                                       uint32_t dst, int tid, int nchunks) {
    for (int g = tid; g < nchunks; g += NT) {
        int row = g >> 5, cg = g & 31;
        const void* gp = src + (size_t)row * ldk + cg * 8;
        uint32_t d = dst + swz512((uint32_t)(row * 512 + cg * 16));
        asm volatile("cp.async.cg.shared.global [%0], [%1], 16;"
                     :: "r"(d), "l"(gp) : "memory");
    }
}

#define CPA_COMMIT() asm volatile("cp.async.commit_group;" ::: "memory")
#define CPA_WAIT(n)  asm volatile("cp.async.wait_group %0;" :: "n"(n) : "memory")

// ------------------------- split fp32 -> bf16 hi/lo ------------------------
__device__ __forceinline__ void split_body(const float* __restrict__ src,
                                           __nv_bfloat16* __restrict__ hi,
                                           __nv_bfloat16* __restrict__ lo, int i)
{
    float4 v = ((const float4*)src)[i];
    __nv_bfloat16 h0 = __float2bfloat16(v.x);
    __nv_bfloat16 h1 = __float2bfloat16(v.y);
    __nv_bfloat16 h2 = __float2bfloat16(v.z);
    __nv_bfloat16 h3 = __float2bfloat16(v.w);
    __nv_bfloat16 l0 = __float2bfloat16(v.x - __bfloat162float(h0));
    __nv_bfloat16 l1 = __float2bfloat16(v.y - __bfloat162float(h1));
    __nv_bfloat16 l2 = __float2bfloat16(v.z - __bfloat162float(h2));
    __nv_bfloat16 l3 = __float2bfloat16(v.w - __bfloat162float(h3));
    __nv_bfloat162* hp = (__nv_bfloat162*)hi;
    __nv_bfloat162* lp = (__nv_bfloat162*)lo;
    hp[2*i]   = __nv_bfloat162{h0, h1};
    hp[2*i+1] = __nv_bfloat162{h2, h3};
    lp[2*i]   = __nv_bfloat162{l0, l1};
    lp[2*i+1] = __nv_bfloat162{l2, l3};
}

__global__ __launch_bounds__(256) void split_kernel(const float* __restrict__ src,
                                                    __nv_bfloat16* __restrict__ hi,
                                                    __nv_bfloat16* __restrict__ lo,
                                                    int n4)
{
    int i = blockIdx.x * 256 + threadIdx.x;
    if (i < n4) split_body(src, hi, lo, i);
}

__global__ __launch_bounds__(256) void wsplit_kernel(
    const float* __restrict__ s0, const float* __restrict__ s1,
    const float* __restrict__ s2, const float* __restrict__ s3,
    __nv_bfloat16* h0, __nv_bfloat16* l0, __nv_bfloat16* h1, __nv_bfloat16* l1,
    __nv_bfloat16* h2, __nv_bfloat16* l2, __nv_bfloat16* h3, __nv_bfloat16* l3)
{
    int i = blockIdx.x * 256 + threadIdx.x;
    if (i >= Dc * Dc / 4) return;
    int z = blockIdx.y;
    const float* s = (z == 0) ? s0 : (z == 1) ? s1 : (z == 2) ? s2 : s3;
    __nv_bfloat16* h = (z == 0) ? h0 : (z == 1) ? h1 : (z == 2) ? h2 : h3;
    __nv_bfloat16* l = (z == 0) ? l0 : (z == 1) ? l1 : (z == 2) ? l2 : l3;
    split_body(s, h, l, i);
}

// ---------------------------------------------------------------------------
// Big GEMM: C[M,N] = A[M,K] @ W[N,K]^T, K = 1024, bf16 split-x3.
// CTA 128x128, 4 warps (2x2 grid) of 64x64 warp tiles: LDSM:HMMA = 1:6.
// BK=32, row-paired 128B-pitch smem, 3 stages x 32KB = 96KB -> 2 CTAs/SM.
// MODE 0: z picks Wq/Wk/Wv; writes bf16 hi/lo head-transposed (Q,K scaled).
// MODE 1: Wo + bias -> plain [BT,D] fp32 to d_out.
// stage layout: Ah 8K | Al 8K | Bh 8K | Bl 8K.
// ---------------------------------------------------------------------------
#define GSTAGE 32768
template <int MODE>
__global__ __launch_bounds__(128, 2) void tc_gemm(
    const __nv_bfloat16* __restrict__ Ahi, const __nv_bfloat16* __restrict__ Alo,
    const __nv_bfloat16* __restrict__ W0h, const __nv_bfloat16* __restrict__ W0l,
    const __nv_bfloat16* __restrict__ W1h, const __nv_bfloat16* __restrict__ W1l,
    const __nv_bfloat16* __restrict__ W2h, const __nv_bfloat16* __restrict__ W2l,
    const float* __restrict__ bias, float* __restrict__ Oplain)
{
    extern __shared__ char smem[];
    const uint32_t sbase = smem_u32(smem);
    const int tid = threadIdx.x, wid = tid >> 5, lane = tid & 31;
    const int bn = blockIdx.x * 128, bm = blockIdx.y * 128;
    const int z = (MODE == 0) ? blockIdx.z : 0;

    const __nv_bfloat16 *Bh, *Bl;
    float scale = 1.0f;
    if (MODE == 0) {
        Bh = (z == 0) ? W0h : ((z == 1) ? W1h : W2h);
        Bl = (z == 0) ? W0l : ((z == 1) ? W1l : W2l);
        scale = (z < 2) ? INV_SQRT_DK : 1.0f;
    } else {
        Bh = W0h; Bl = W0l;
    }

    auto load_stage = [&](int c, int stg) {
        uint32_t st = sbase + (uint32_t)stg * (uint32_t)GSTAGE;
        int k0 = c * 32;
        cpa_p<128>(Ahi + (size_t)bm * Dc + k0, Dc, st,          tid, 512);
        cpa_p<128>(Alo + (size_t)bm * Dc + k0, Dc, st + 8192,   tid, 512);
        cpa_p<128>(Bh  + (size_t)bn * Dc + k0, Dc, st + 16384,  tid, 512);
        cpa_p<128>(Bl  + (size_t)bn * Dc + k0, Dc, st + 24576,  tid, 512);
        CPA_COMMIT();
    };

    float acc[4][8][4];
#pragma unroll
    for (int a = 0; a < 4; a++)
#pragma unroll
        for (int b = 0; b < 8; b++)
#pragma unroll
            for (int c = 0; c < 4; c++) acc[a][b][c] = 0.0f;

    const int wm = wid & 1, wn = wid >> 1;
    const int arl = lane & 15;              // A fragment row-in-tile
    const int ach = lane >> 4;              // A k-half
    const int brl = ((lane >> 4) << 3) + (lane & 7);  // B row-in-tile
    const int bch = (lane >> 3) & 1;        // B k-half

    load_stage(0, 0);
    load_stage(1, 1);

    for (int c = 0; c < 32; c++) {
        if (c < 31) { CPA_WAIT(1); } else { CPA_WAIT(0); }
        __syncthreads();
        if (c + 2 < 32) load_stage(c + 2, (c + 2) % 3);

        const uint32_t st = sbase + (uint32_t)(c % 3) * (uint32_t)GSTAGE;
#pragma unroll
        for (int ks2 = 0; ks2 < 2; ks2++) {
            uint32_t ah[4][4], al[4][4], bhf[4][4], blf[4][4];
#pragma unroll
            for (int mb = 0; mb < 4; mb++) {
                int r = wm * 64 + mb * 16 + arl;
                uint32_t off = swz_b((uint32_t)((r >> 1) * 128 + (r & 1) * 64
                                                + (ks2 * 2 + ach) * 16));
                ldsm_x4(ah[mb], st + off);
                ldsm_x4(al[mb], st + 8192 + off);
            }
#pragma unroll
            for (int nt = 0; nt < 4; nt++) {
                int r = wn * 64 + nt * 16 + brl;
                uint32_t off = swz_b((uint32_t)((r >> 1) * 128 + (r & 1) * 64
                                                + (ks2 * 2 + bch) * 16));
                ldsm_x4(bhf[nt], st + 16384 + off);
                ldsm_x4(blf[nt], st + 24576 + off);
            }
            // pass-major: hh, hl, lh — per-accumulator order matches prior rounds
#pragma unroll
            for (int mb = 0; mb < 4; mb++)
#pragma unroll
                for (int nb = 0; nb < 8; nb++)
                    mma_bf16(acc[mb][nb], ah[mb], &bhf[nb >> 1][(nb & 1) * 2]);
#pragma unroll
            for (int mb = 0; mb < 4; mb++)
#pragma unroll
                for (int nb = 0; nb < 8; nb++)
                    mma_bf16(acc[mb][nb], ah[mb], &blf[nb >> 1][(nb & 1) * 2]);
#pragma unroll
            for (int mb = 0; mb < 4; mb++)
#pragma unroll
                for (int nb = 0; nb < 8; nb++)
                    mma_bf16(acc[mb][nb], al[mb], &bhf[nb >> 1][(nb & 1) * 2]);
        }
        __syncthreads();
    }

    // ---- epilogue ----
    const int group = lane >> 2, tig = lane & 3;
#pragma unroll
    for (int mb = 0; mb < 4; mb++) {
        int m0 = bm + wm * 64 + mb * 16 + group;
#pragma unroll
        for (int nb = 0; nb < 8; nb++) {
            int n0 = bn + wn * 64 + nb * 8 + tig * 2;
            float* d = acc[mb][nb];
            if (MODE == 0) {
                int head = n0 >> 6, dd = n0 & 63;
                int bb = m0 >> 12, t = m0 & (Tc - 1);
                size_t base = ((((size_t)bb * Hc + head) * Tc) + t) * DKc + dd;
                __nv_bfloat16* qh = (z == 0) ? g_Qh : ((z == 1) ? g_Kh : g_Vh);
                __nv_bfloat16* ql = (z == 0) ? g_Ql : ((z == 1) ? g_Kl : g_Vl);
                split_store(qh, ql, base,           d[0] * scale, d[1] * scale);
                split_store(qh, ql, base + 8 * DKc, d[2] * scale, d[3] * scale);
            } else {
                float2 bv = *(const float2*)(bias + n0);
                float* o = Oplain + (size_t)m0 * Dc + n0;
                *(float2*)o           = make_float2(d[0] + bv.x, d[1] + bv.y);
                *(float2*)(o + 8*Dc)  = make_float2(d[2] + bv.x, d[3] + bv.y);
            }
        }
    }
}

// ---------------------------------------------------------------------------
// phi via mma: xw[128t x 256m] = X[128 x 64] @ proj[256 x 64]^T (split-x3),
// then rowmax/exp epilogue. z=0: Q -> phiQ hi/lo. z=1: K -> phiK hi/lo +
// per-tile column sums (Ksum partials, fp32, deterministic tree).
// ---------------------------------------------------------------------------
#define PHI_SMEM (98304 + 8192)
__global__ __launch_bounds__(256, 1) void phi_mma()
{
    extern __shared__ char smem[];
    const uint32_t sbase = smem_u32(smem);
    float* sKs = (float*)(smem + 98304);
    const int tid = threadIdx.x, wid = tid >> 5, lane = tid & 31;
    const int bh = blockIdx.x, tile = blockIdx.y, z = blockIdx.z;
    const int h = bh & (Hc - 1);

    const __nv_bfloat16* Ah = z ? g_Kh : g_Qh;
    const __nv_bfloat16* Al = z ? g_Kl : g_Ql;

    const size_t abase = ((size_t)bh * Tc + tile * 128) * DKc;
    cpa_g<256>(Ah + abase, DKc, sbase,         tid, 1024);
    cpa_g<256>(Al + abase, DKc, sbase + 16384, tid, 1024);
    const size_t pbase = (size_t)h * Mc * DKc;
    cpa_g<256>(g_ph + pbase, DKc, sbase + 32768, tid, 2048);
    cpa_g<256>(g_pl + pbase, DKc, sbase + 65536, tid, 2048);
    CPA_COMMIT();
    CPA_WAIT(0);
    __syncthreads();

    float acc[32][4];
#pragma unroll
    for (int nb = 0; nb < 32; nb++)
#pragma unroll
        for (int j = 0; j < 4; j++) acc[nb][j] = 0.0f;

    const int m0 = wid * 16;
    const uint32_t arow = (uint32_t)(m0 + (lane & 15));
    const uint32_t akh  = (uint32_t)((lane >> 4) << 3);
    const uint32_t brw  = (uint32_t)(((lane >> 4) << 3) + (lane & 7));
    const uint32_t bkh  = (uint32_t)(lane & 8);

#pragma unroll
    for (int ks = 0; ks < 4; ks++) {
        uint32_t ah[4], al[4];
        uint32_t aoff = swz_b(arow * 128 + (ks * 16 + akh) * 2);
        ldsm_x4(ah, sbase + aoff);
        ldsm_x4(al, sbase + 16384 + aoff);
#pragma unroll
        for (int nb4 = 0; nb4 < 8; nb4++) {
            uint32_t b4h[2][4], b4l[2][4];
#pragma unroll
            for (int q = 0; q < 2; q++) {
                uint32_t boff = swz_b(((nb4 * 2 + q) * 16 + brw) * 128 + (ks * 16 + bkh) * 2);
                ldsm_x4(b4h[q], sbase + 32768 + boff);
                ldsm_x4(b4l[q], sbase + 65536 + boff);
            }
#pragma unroll
            for (int q = 0; q < 2; q++)
#pragma unroll
                for (int w = 0; w < 2; w++)
                    mma_bf16(acc[(nb4 * 2 + q) * 2 + w], ah, &b4h[q][w * 2]);
#pragma unroll
            for (int q = 0; q < 2; q++)
#pragma unroll
                for (int w = 0; w < 2; w++)
                    mma_bf16(acc[(nb4 * 2 + q) * 2 + w], ah, &b4l[q][w * 2]);
#pragma unroll
            for (int q = 0; q < 2; q++)
#pragma unroll
                for (int w = 0; w < 2; w++)
                    mma_bf16(acc[(nb4 * 2 + q) * 2 + w], al, &b4h[q][w * 2]);
        }
    }

    // ---- epilogue: rowmax, xnorm, exp, store (+Ksum for z=1) ----
    const int group = lane >> 2, tig = lane & 3;
    float mx0 = -1e30f, mx1 = -1e30f;
#pragma unroll
    for (int nb = 0; nb < 32; nb++) {
        mx0 = fmaxf(mx0, fmaxf(acc[nb][0], acc[nb][1]));
        mx1 = fmaxf(mx1, fmaxf(acc[nb][2], acc[nb][3]));
    }
#pragma unroll
    for (int o = 1; o < 4; o <<= 1) {
        mx0 = fmaxf(mx0, __shfl_xor_sync(0xffffffffu, mx0, o));
        mx1 = fmaxf(mx1, __shfl_xor_sync(0xffffffffu, mx1, o));
    }

    auto rowsq = [&](int r) -> float {
        float s = 0.0f;
#pragma unroll
        for (int cg = 0; cg < 8; cg++) {
            uint32_t off = swz_b((uint32_t)(r * 128 + cg * 16));
            uint4 hv = *(const uint4*)(smem + off);
            uint4 lv = *(const uint4*)(smem + 16384 + off);
            const __nv_bfloat162* hp = (const __nv_bfloat162*)&hv;
            const __nv_bfloat162* lp = (const __nv_bfloat162*)&lv;
#pragma unroll
            for (int j = 0; j < 4; j++) {
                float2 hf = __bfloat1622float2(hp[j]);
                float2 lf = __bfloat1622float2(lp[j]);
                float a = hf.x + lf.x, b = hf.y + lf.y;
                s += a * a + b * b;
            }
        }
        return s;
    };
    const int r0l = m0 + group, r1l = r0l + 8;
    float e0 = expf(-0.5f * rowsq(r0l));
    float e1 = expf(-0.5f * rowsq(r1l));

    __nv_bfloat16* ph = z ? g_pKh : g_pQh;
    __nv_bfloat16* pl = z ? g_pKl : g_pQl;
    const size_t idx0 = ((size_t)bh * Tc + tile * 128 + r0l) * Mc;
    const size_t idx1 = ((size_t)bh * Tc + tile * 128 + r1l) * Mc;
#pragma unroll
    for (int nb = 0; nb < 32; nb++) {
        int col = nb * 8 + tig * 2;
        float v00 = (expf(acc[nb][0] - mx0) * e0 + EPSc) * INV_SQRT_M;
        float v01 = (expf(acc[nb][1] - mx0) * e0 + EPSc) * INV_SQRT_M;
        float v10 = (expf(acc[nb][2] - mx1) * e1 + EPSc) * INV_SQRT_M;
        float v11 = (expf(acc[nb][3] - mx1) * e1 + EPSc) * INV_SQRT_M;
        split_store(ph, pl, idx0 + col, v00, v01);
        split_store(ph, pl, idx1 + col, v10, v11);
        if (z == 1) {
            float cs0 = v00 + v10, cs1 = v01 + v11;
#pragma unroll
            for (int o = 4; o < 32; o <<= 1) {
                cs0 += __shfl_xor_sync(0xffffffffu, cs0, o);
                cs1 += __shfl_xor_sync(0xffffffffu, cs1, o);
            }
            if (lane < 4) {
                sKs[wid * 256 + nb * 8 + lane * 2]     = cs0;
                sKs[wid * 256 + nb * 8 + lane * 2 + 1] = cs1;
            }
        }
    }
    if (z == 1) {
        __syncthreads();
        float s = 0.0f;
#pragma unroll
        for (int w = 0; w < 8; w++) s += sKs[w * 256 + tid];
        g_Ksp[((size_t)tile * BHc + bh) * Mc + tid] = s;
    }
}

// ---------------------------------------------------------------------------
// kv via mma: KV[m=256, dk=64] = phiK^T[m,t] @ V[t,dk], 16 chunks of 256.
// Both operands t-major -> ldmatrix.trans frags. 8 warps, warp 64x32.
// ---------------------------------------------------------------------------
#define KVSTAGE 40960
__global__ __launch_bounds__(256, 2) void kv_mma()
{
    extern __shared__ char smem[];
    const uint32_t sbase = smem_u32(smem);
    const int tid = threadIdx.x, wid = tid >> 5, lane = tid & 31;
    const int bh = blockIdx.x, chunk = blockIdx.y;
    const int wm = wid & 3, wn = wid >> 2;

    const size_t pbase = ((size_t)bh * Tc + chunk * 256) * Mc;
    const size_t vbase = ((size_t)bh * Tc + chunk * 256) * DKc;

    auto load_stage = [&](int s, int stg) {
        uint32_t st = sbase + (uint32_t)stg * (uint32_t)KVSTAGE;
        cpa512<256>(g_pKh + pbase + (size_t)s * 32 * Mc, Mc, st,          tid, 1024);
        cpa512<256>(g_pKl + pbase + (size_t)s * 32 * Mc, Mc, st + 16384, tid, 1024);
        cpa_g<256>(g_Vh + vbase + (size_t)s * 32 * DKc, DKc, st + 32768, tid, 256);
        cpa_g<256>(g_Vl + vbase + (size_t)s * 32 * DKc, DKc, st + 36864, tid, 256);
        CPA_COMMIT();
    };

    float acc[4][4][4];
#pragma unroll
    for (int a = 0; a < 4; a++)
#pragma unroll
        for (int b = 0; b < 4; b++)
#pragma unroll
            for (int c = 0; c < 4; c++) acc[a][b][c] = 0.0f;

    const int krA = ((lane >> 4) & 1) * 8 + (lane & 7);
    const int mA  = ((lane >> 3) & 1) * 8;
    const int krB = ((lane >> 3) & 1) * 8 + (lane & 7);
    const int nB  = ((lane >> 4) & 1) * 8;

    load_stage(0, 0);

    for (int s = 0; s < 8; s++) {
        if (s + 1 < 8) { load_stage(s + 1, (s + 1) & 1); CPA_WAIT(1); }
        else           { CPA_WAIT(0); }
        __syncthreads();

        const uint32_t st = sbase + (uint32_t)(s & 1) * (uint32_t)KVSTAGE;
#pragma unroll
        for (int kk = 0; kk < 32; kk += 16) {
            uint32_t ah[4][4], al[4][4], bhf[2][4], blf[2][4];
#pragma unroll
            for (int mb = 0; mb < 4; mb++) {
                int mc = wm * 64 + mb * 16 + mA;
                uint32_t off = swz512((uint32_t)((kk + krA) * 512 + mc * 2));
                ldsm_x4_t(ah[mb], st + off);
                ldsm_x4_t(al[mb], st + 16384 + off);
            }
#pragma unroll
            for (int nb2 = 0; nb2 < 2; nb2++) {
                int nc = wn * 32 + nb2 * 16 + nB;
                uint32_t off = swz_b((uint32_t)((kk + krB) * 128 + nc * 2));
                ldsm_x4_t(bhf[nb2], st + 32768 + off);
                ldsm_x4_t(blf[nb2], st + 36864 + off);
            }
#pragma unroll
            for (int mb = 0; mb < 4; mb++)
#pragma unroll
                for (int nb = 0; nb < 4; nb++)
                    mma_bf16(acc[mb][nb], ah[mb], &bhf[nb >> 1][(nb & 1) * 2]);
#pragma unroll
            for (int mb = 0; mb < 4; mb++)
#pragma unroll
                for (int nb = 0; nb < 4; nb++)
                    mma_bf16(acc[mb][nb], ah[mb], &blf[nb >> 1][(nb & 1) * 2]);
#pragma unroll
            for (int mb = 0; mb < 4; mb++)
#pragma unroll
                for (int nb = 0; nb < 4; nb++)
                    mma_bf16(acc[mb][nb], al[mb], &bhf[nb >> 1][(nb & 1) * 2]);
        }
        __syncthreads();
    }

    // ---- partials ----
    const int group = lane >> 2, tig = lane & 3;
    float* o = g_KVp + ((size_t)chunk * BHc + bh) * (Mc * DKc);
#pragma unroll
    for (int mb = 0; mb < 4; mb++) {
        int m0 = wm * 64 + mb * 16 + group;
#pragma unroll
        for (int nb = 0; nb < 4; nb++) {
            int n0 = wn * 32 + nb * 8 + tig * 2;
            float* d = acc[mb][nb];
            *(float2*)(o + (size_t)m0 * DKc + n0)       = make_float2(d[0], d[1]);
            *(float2*)(o + (size_t)(m0 + 8) * DKc + n0) = make_float2(d[2], d[3]);
        }
    }
}

// Reduce partials -> KVaug [bh][72][256] bf16 hi/lo.
__global__ __launch_bounds__(256) void kv_reduce()
{
    int i = blockIdx.x * 256 + threadIdx.x;
    if (i < BHc * Mc * DKc) {
        float s = 0.0f;
#pragma unroll
        for (int c = 0; c < KVCH; c++) s += g_KVp[(size_t)c * (BHc * Mc * DKc) + i];
        int bh = i >> 14, rem = i & 16383, m = rem >> 6, dd = rem & 63;
        size_t o = ((size_t)bh * NAUG + dd) * Mc + m;
        __nv_bfloat16 hi = __float2bfloat16(s);
        g_kvh[o] = hi;
        g_kvl[o] = __float2bfloat16(s - __bfloat162float(hi));
    }
    if (i < BHc * Mc) {
        float s = 0.0f;
#pragma unroll
        for (int c = 0; c < KSTILE; c++) s += g_Ksp[(size_t)c * (BHc * Mc) + i];
        int bh = i >> 8, m = i & 255;
        size_t o = ((size_t)bh * NAUG + 64) * Mc + m;
        __nv_bfloat16 hi = __float2bfloat16(s);
        g_kvh[o] = hi;
        g_kvl[o] = __float2bfloat16(s - __bfloat162float(hi));
    }
    if (i < BHc * 7 * Mc) {
        int bh = i / (7 * Mc), r = i % (7 * Mc);
        size_t o = ((size_t)bh * NAUG + 65 + r / Mc) * Mc + (r % Mc);
        g_kvh[o] = __float2bfloat16(0.0f);
        g_kvl[o] = __float2bfloat16(0.0f);
    }
}

// ---------------------------------------------------------------------------
// num via mma: out[128t x 72] = phiQ[128 x 256] @ KVaug[72 x 256]^T.
// Col 64 = den. Epilogue divides, writes merged as bf16 hi/lo.
// ---------------------------------------------------------------------------
#define NUM_STAGE 53248
__global__ __launch_bounds__(256, 1) void num_mma()
{
    extern __shared__ char smem[];
    const uint32_t sbase = smem_u32(smem);
    const int tid = threadIdx.x, wid = tid >> 5, lane = tid & 31;
    const int bh = blockIdx.x, tile = blockIdx.y;
    const int b = bh >> 4, h = bh & (Hc - 1);

    {
        int g = tid;
        int stg = g >> 7, rem = g & 127, buf = rem >> 6, c = rem & 63;
        uint32_t off = (uint32_t)(stg * NUM_STAGE + 32768 + buf * 10240 + 9216 + c * 16);
        *(uint4*)(smem + off) = make_uint4(0, 0, 0, 0);
    }

    const size_t abase = ((size_t)bh * Tc + tile * 128) * Mc;
    const size_t bbase = (size_t)bh * NAUG * Mc;

    auto load_stage = [&](int c, int buf) {
        uint32_t st = sbase + (uint32_t)buf * NUM_STAGE;
        int k0 = c * 64;
        cpa_g<256>(g_pQh + abase + k0, Mc, st,          tid, 1024);
        cpa_g<256>(g_pQl + abase + k0, Mc, st + 16384,  tid, 1024);
        cpa_g<256>(g_kvh + bbase + k0, Mc, st + 32768,  tid, 576);
        cpa_g<256>(g_kvl + bbase + k0, Mc, st + 43008,  tid, 576);
        CPA_COMMIT();
    };

    float acc[9][4];
#pragma unroll
    for (int nb = 0; nb < 9; nb++)
#pragma unroll
        for (int j = 0; j < 4; j++) acc[nb][j] = 0.0f;

    const int m0 = wid * 16;
    const uint32_t arow = (uint32_t)(m0 + (lane & 15));
    const uint32_t akh  = (uint32_t)((lane >> 4) << 3);
    const uint32_t brw  = (uint32_t)(((lane >> 4) << 3) + (lane & 7));
    const uint32_t bkh  = (uint32_t)(lane & 8);

    load_stage(0, 0);

    for (int c = 0; c < 4; c++) {
        if (c + 1 < 4) { load_stage(c + 1, (c + 1) & 1); CPA_WAIT(1); }
        else           { CPA_WAIT(0); }
        __syncthreads();

        const uint32_t st = sbase + (uint32_t)(c & 1) * NUM_STAGE;
#pragma unroll
        for (int ks = 0; ks < 4; ks++) {
            uint32_t ah[4], al[4];
            uint32_t aoff = swz_b(arow * 128 + (ks * 16 + akh) * 2);
            ldsm_x4(ah, st + aoff);
            ldsm_x4(al, st + 16384 + aoff);
            uint32_t b4h[5][4], b4l[5][4];
#pragma unroll
            for (int nb2 = 0; nb2 < 5; nb2++) {
                uint32_t boff = swz_b((nb2 * 16 + brw) * 128 + (ks * 16 + bkh) * 2);
                ldsm_x4(b4h[nb2], st + 32768 + boff);
                ldsm_x4(b4l[nb2], st + 43008 + boff);
            }
#pragma unroll
            for (int nb = 0; nb < 9; nb++)
                mma_bf16(acc[nb], ah, &b4h[nb >> 1][(nb & 1) * 2]);
#pragma unroll
            for (int nb = 0; nb < 9; nb++)
                mma_bf16(acc[nb], ah, &b4l[nb >> 1][(nb & 1) * 2]);
#pragma unroll
            for (int nb = 0; nb < 9; nb++)
                mma_bf16(acc[nb], al, &b4h[nb >> 1][(nb & 1) * 2]);
        }
        __syncthreads();
    }

    const int group = lane >> 2, tig = lane & 3;
    float den0 = __shfl_sync(0xffffffffu, acc[8][0], lane & ~3);
    float den1 = __shfl_sync(0xffffffffu, acc[8][2], lane & ~3);
    float inv0 = 1.0f / (den0 + EPSc);
    float inv1 = 1.0f / (den1 + EPSc);

    const int t0 = tile * 128 + m0 + group;
    const size_t row0 = (size_t)(b * Tc + t0) * Dc + h * DKc;
    const size_t row1 = row0 + (size_t)8 * Dc;
#pragma unroll
    for (int nb = 0; nb < 8; nb++) {
        int col = nb * 8 + tig * 2;
        split_store(g_mhi, g_mlo, row0 + col, acc[nb][0] * inv0, acc[nb][1] * inv0);
        split_store(g_mhi, g_mlo, row1 + col, acc[nb][2] * inv1, acc[nb][3] * inv1);
    }
}

// ------------------------- launch ------------------------------------------
extern "C" void kernel_launch(void* const* d_in, const int* in_sizes, int n_in,
                              void* d_out, int out_size)
{
    const float* x    = (const float*)d_in[0];
    const float* Wq   = (const float*)d_in[1];
    const float* Wk   = (const float*)d_in[2];
    const float* Wv   = (const float*)d_in[3];
    const float* Wo   = (const float*)d_in[4];
    const float* bo   = (const float*)d_in[5];
    const float* proj = (const float*)d_in[6];
    float* out = (float*)d_out;

    __nv_bfloat16 *xhi, *xlo, *mhi, *mlo, *ph, *pl;
    __nv_bfloat16 *wqh, *wql, *wkh, *wkl, *wvh, *wvl, *woh, *wol;
    cudaGetSymbolAddress((void**)&xhi, g_xhi); cudaGetSymbolAddress((void**)&xlo, g_xlo);
    cudaGetSymbolAddress((void**)&mhi, g_mhi); cudaGetSymbolAddress((void**)&mlo, g_mlo);
    cudaGetSymbolAddress((void**)&ph,  g_ph);  cudaGetSymbolAddress((void**)&pl,  g_pl);
    cudaGetSymbolAddress((void**)&wqh, g_wqh); cudaGetSymbolAddress((void**)&wql, g_wql);
    cudaGetSymbolAddress((void**)&wkh, g_wkh); cudaGetSymbolAddress((void**)&wkl, g_wkl);
    cudaGetSymbolAddress((void**)&wvh, g_wvh); cudaGetSymbolAddress((void**)&wvl, g_wvl);
    cudaGetSymbolAddress((void**)&woh, g_woh); cudaGetSymbolAddress((void**)&wol, g_wol);

    const int GEMM_SMEM = 3 * GSTAGE;     // 96 KB -> 2 CTAs/SM
    const int NUM_SMEM  = 2 * NUM_STAGE;  // 104 KB
    const int KV_SMEM   = 2 * KVSTAGE;    // 80 KB
    cudaFuncSetAttribute(tc_gemm<0>, cudaFuncAttributeMaxDynamicSharedMemorySize, GEMM_SMEM);
    cudaFuncSetAttribute(tc_gemm<1>, cudaFuncAttributeMaxDynamicSharedMemorySize, GEMM_SMEM);
    cudaFuncSetAttribute(phi_mma,    cudaFuncAttributeMaxDynamicSharedMemorySize, PHI_SMEM);
    cudaFuncSetAttribute(kv_mma,     cudaFuncAttributeMaxDynamicSharedMemorySize, KV_SMEM);
    cudaFuncSetAttribute(num_mma,    cudaFuncAttributeMaxDynamicSharedMemorySize, NUM_SMEM);

    // 0) split fp32 operands into bf16 hi/lo
    split_kernel<<<(BTc * Dc / 4 + 255) / 256, 256>>>(x, xhi, xlo, BTc * Dc / 4);
    wsplit_kernel<<<dim3((Dc * Dc / 4 + 255) / 256, 4), 256>>>(
        Wq, Wk, Wv, Wo, wqh, wql, wkh, wkl, wvh, wvl, woh, wol);
    split_kernel<<<(Hc * Mc * DKc / 4 + 255) / 256, 256>>>(proj, ph, pl, Hc * Mc * DKc / 4);

    // 1) Q/K/V projections -> bf16 hi/lo head-transposed (Q,K scaled)
    tc_gemm<0><<<dim3(Dc / 128, BTc / 128, 3), 128, GEMM_SMEM>>>(
        xhi, xlo, wqh, wql, wkh, wkl, wvh, wvl, nullptr, nullptr);

    // 2) FAVOR+ features (phiQ / phiK hi/lo, Ksum partials from z=1)
    phi_mma<<<dim3(BHc, Tc / 128, 2), 256, PHI_SMEM>>>();

    // 3) KV reduction on tensor cores + merge to KVaug
    kv_mma<<<dim3(BHc, KVCH), 256, KV_SMEM>>>();
    kv_reduce<<<(BHc * Mc * DKc + 255) / 256, 256>>>();

    // 4) numerator/denominator -> merged bf16 hi/lo
    num_mma<<<dim3(BHc, Tc / 128), 256, NUM_SMEM>>>();

    // 5) output projection
    tc_gemm<1><<<dim3(Dc / 128, BTc / 128, 1), 128, GEMM_SMEM>>>(
        mhi, mlo, woh, wol, nullptr, nullptr, nullptr, nullptr, bo, out);
}